// round 3
// baseline (speedup 1.0000x reference)
#include <cuda_runtime.h>
#include <cstdint>

#define NB  32
#define ND  128
#define NCL 1024
#define NQL 512

// ---------------- scratch (device globals: allocation-free) ----------------
__device__ float g_Aeff[(size_t)NB * NCL * ND];     // 16.8 MB  Aeff[b][c][d]
__device__ float g_bias[(size_t)NB * NCL];          //  bias[b][c]
__device__ float g_S  [(size_t)NB * NCL * NQL];     // 67 MB   S[b][c][q]
__device__ float g_S1 [(size_t)NB * NCL * NQL];     // 67 MB
__device__ float g_S2 [(size_t)NB * NCL * NQL];     // 67 MB
__device__ float g_T  [(size_t)NB * ND * NQL];      // 8.4 MB  T[b][d][q] = S2tC^T
__device__ float g_At [(size_t)NB * ND * NCL];      // 16.8 MB A^T[b][d][c]
__device__ float g_Bmt[(size_t)NB * ND * NCL];      // 16.8 MB Bm^T[b][d][c]

// ---------------- K0: Aeff = wq + wqc*Ct ; bias = wc . Ct -------------------
// grid (NCL/32, NB), 256 threads. C tile staged through smem (transposed).
__global__ __launch_bounds__(256) void prep_kernel(
    const float* __restrict__ C, const float* __restrict__ W,
    float* __restrict__ Aeff, float* __restrict__ bias)
{
    __shared__ float Csm[ND][33];           // [d][c], pad 33 -> conflict-free
    const int b  = blockIdx.y;
    const int c0 = blockIdx.x * 32;
    const int t  = threadIdx.x;
    const float* Cb = C + (size_t)b * ND * NCL;

    #pragma unroll
    for (int i = 0; i < 16; i++) {          // 128 d x 32 c = 4096 elems
        int idx = i * 256 + t;
        int d = idx >> 5, c = idx & 31;
        Csm[d][c] = Cb[(size_t)d * NCL + c0 + c];   // c-fast: coalesced
    }
    __syncthreads();

    #pragma unroll
    for (int i = 0; i < 16; i++) {
        int idx = i * 256 + t;
        int c = idx >> 7, d = idx & 127;
        size_t wb = (size_t)(b * NCL + c0 + c) * 384;
        float wq  = W[wb + d];
        float wqc = W[wb + 256 + d];
        Aeff[(size_t)(b * NCL + c0 + c) * ND + d] = wq + wqc * Csm[d][c];
    }

    // bias: warp w handles rows c = w, w+8, w+16, w+24
    int w = t >> 5, lane = t & 31;
    #pragma unroll
    for (int j = 0; j < 4; j++) {
        int c = w + j * 8;
        size_t wb = (size_t)(b * NCL + c0 + c) * 384 + 128;
        float s = 0.f;
        #pragma unroll
        for (int jj = 0; jj < 4; jj++) {
            int d = lane + jj * 32;
            s += W[wb + d] * Csm[d][c];
        }
        #pragma unroll
        for (int off = 16; off; off >>= 1)
            s += __shfl_xor_sync(0xffffffffu, s, off);
        if (lane == 0) bias[b * NCL + c0 + c] = s;
    }
}

// ---------------- batched tiled fp32 GEMM ----------------------------------
// Cout[M x N] = A[M x K rm] @ B, where B is K x N rm (TRANSB=false)
// or stored as N x K rm (TRANSB=true, transposed on smem load).
// 256 threads, thread tile (BM/16) x (BN/16), float4 everywhere.
template <int BM, int BN, bool TRANSB>
__global__ __launch_bounds__(256) void gemm_tpl(
    const float* __restrict__ Aall, const float* __restrict__ Ball,
    float* __restrict__ Call,
    int M, int N, int K,
    size_t aStride, size_t bStride, size_t cStride)
{
    constexpr int BK = 16;
    constexpr int TM = BM / 16, TN = BN / 16;
    constexpr int MG = TM / 4,  NG = TN / 4;
    constexpr int MSTEP = BM / MG, NSTEP = BN / NG;

    __shared__ float As[BK][BM + 4];
    __shared__ float Bs[BK][BN + 4];

    const int b  = blockIdx.z;
    const int m0 = blockIdx.y * BM;
    const int n0 = blockIdx.x * BN;
    const float* A  = Aall + (size_t)b * aStride + (size_t)m0 * K;
    const float* Bp = Ball + (size_t)b * bStride;
    float*       Cm = Call + (size_t)b * cStride;

    const int tid = threadIdx.x;
    const int tx = tid & 15, ty = tid >> 4;

    float acc[TM][TN] = {};
    float ar[TM], br[TN];

    for (int k0 = 0; k0 < K; k0 += BK) {
        // A tile: BM x 16, float4 along k, scatter-transpose into As[k][m]
        #pragma unroll
        for (int i = 0; i < (BM * 4) / 256; i++) {
            int lid = tid + i * 256;
            int r = lid >> 2, kq = lid & 3;
            float4 v = *(const float4*)(A + (size_t)r * K + k0 + kq * 4);
            As[kq * 4 + 0][r] = v.x; As[kq * 4 + 1][r] = v.y;
            As[kq * 4 + 2][r] = v.z; As[kq * 4 + 3][r] = v.w;
        }
        if (TRANSB) {
            #pragma unroll
            for (int i = 0; i < (BN * 4) / 256; i++) {
                int lid = tid + i * 256;
                int r = lid >> 2, kq = lid & 3;
                float4 v = *(const float4*)(Bp + (size_t)(n0 + r) * K + k0 + kq * 4);
                Bs[kq * 4 + 0][r] = v.x; Bs[kq * 4 + 1][r] = v.y;
                Bs[kq * 4 + 2][r] = v.z; Bs[kq * 4 + 3][r] = v.w;
            }
        } else {
            #pragma unroll
            for (int i = 0; i < (BK * BN / 4) / 256; i++) {
                int lid = tid + i * 256;
                int r = lid / (BN / 4), q = lid % (BN / 4);
                float4 v = *(const float4*)(Bp + (size_t)(k0 + r) * N + n0 + q * 4);
                *(float4*)&Bs[r][q * 4] = v;
            }
        }
        __syncthreads();

        #pragma unroll
        for (int k = 0; k < BK; k++) {
            #pragma unroll
            for (int g = 0; g < MG; g++) {
                float4 v = *(const float4*)&As[k][g * MSTEP + ty * 4];
                ar[g*4+0]=v.x; ar[g*4+1]=v.y; ar[g*4+2]=v.z; ar[g*4+3]=v.w;
            }
            #pragma unroll
            for (int g = 0; g < NG; g++) {
                float4 v = *(const float4*)&Bs[k][g * NSTEP + tx * 4];
                br[g*4+0]=v.x; br[g*4+1]=v.y; br[g*4+2]=v.z; br[g*4+3]=v.w;
            }
            #pragma unroll
            for (int mi = 0; mi < TM; mi++)
                #pragma unroll
                for (int ni = 0; ni < TN; ni++)
                    acc[mi][ni] = fmaf(ar[mi], br[ni], acc[mi][ni]);
        }
        __syncthreads();
    }

    #pragma unroll
    for (int mg = 0; mg < MG; mg++)
        #pragma unroll
        for (int i = 0; i < 4; i++) {
            int m = m0 + mg * MSTEP + ty * 4 + i;
            #pragma unroll
            for (int ng = 0; ng < NG; ng++) {
                float4 v;
                v.x = acc[mg*4+i][ng*4+0]; v.y = acc[mg*4+i][ng*4+1];
                v.z = acc[mg*4+i][ng*4+2]; v.w = acc[mg*4+i][ng*4+3];
                *(float4*)&Cm[(size_t)m * N + n0 + ng * NSTEP + tx * 4] = v;
            }
        }
}

// ---------------- K2a: row softmax over q (bias cancels) --------------------
// one warp per row of 512; 8 warps/block
__global__ __launch_bounds__(256) void row_softmax_k(
    const float* __restrict__ S, float* __restrict__ O)
{
    int row  = blockIdx.x * 8 + (threadIdx.x >> 5);
    int lane = threadIdx.x & 31;
    const float4* src = (const float4*)(S + (size_t)row * NQL);
    float4* dst = (float4*)(O + (size_t)row * NQL);

    float4 v[4];
    float mx = -1e30f;
    #pragma unroll
    for (int i = 0; i < 4; i++) {
        v[i] = src[lane + i * 32];
        mx = fmaxf(mx, fmaxf(fmaxf(v[i].x, v[i].y), fmaxf(v[i].z, v[i].w)));
    }
    #pragma unroll
    for (int off = 16; off; off >>= 1)
        mx = fmaxf(mx, __shfl_xor_sync(0xffffffffu, mx, off));

    float s = 0.f;
    #pragma unroll
    for (int i = 0; i < 4; i++) {
        v[i].x = __expf(v[i].x - mx); v[i].y = __expf(v[i].y - mx);
        v[i].z = __expf(v[i].z - mx); v[i].w = __expf(v[i].w - mx);
        s += v[i].x + v[i].y + v[i].z + v[i].w;
    }
    #pragma unroll
    for (int off = 16; off; off >>= 1)
        s += __shfl_xor_sync(0xffffffffu, s, off);
    float inv = 1.f / s;
    #pragma unroll
    for (int i = 0; i < 4; i++) {
        v[i].x *= inv; v[i].y *= inv; v[i].z *= inv; v[i].w *= inv;
        dst[lane + i * 32] = v[i];
    }
}

// ---------------- K2b: column softmax over c (includes bias) ----------------
// grid (NQL/64, NB), 64 threads; thread owns one q column (coalesced per c).
__global__ __launch_bounds__(64) void col_softmax_k(
    const float* __restrict__ S, const float* __restrict__ bias,
    float* __restrict__ S2)
{
    __shared__ float bsm[NCL];
    const int b = blockIdx.y;
    const int q = blockIdx.x * 64 + threadIdx.x;
    const float* bp = bias + b * NCL;
    for (int i = threadIdx.x; i < NCL; i += 64) bsm[i] = bp[i];
    __syncthreads();

    const float* src = S  + (size_t)b * NCL * NQL + q;
    float*       dst = S2 + (size_t)b * NCL * NQL + q;

    float m = -1e30f, l = 0.f;
    for (int c = 0; c < NCL; c += 4) {
        float v0 = src[(size_t)(c+0) * NQL] + bsm[c+0];
        float v1 = src[(size_t)(c+1) * NQL] + bsm[c+1];
        float v2 = src[(size_t)(c+2) * NQL] + bsm[c+2];
        float v3 = src[(size_t)(c+3) * NQL] + bsm[c+3];
        float nm = fmaxf(m, fmaxf(fmaxf(v0, v1), fmaxf(v2, v3)));
        l = l * __expf(m - nm)
          + __expf(v0 - nm) + __expf(v1 - nm) + __expf(v2 - nm) + __expf(v3 - nm);
        m = nm;
    }
    float inv = 1.f / l;
    for (int c = 0; c < NCL; c += 4) {
        float v0 = src[(size_t)(c+0) * NQL] + bsm[c+0];
        float v1 = src[(size_t)(c+1) * NQL] + bsm[c+1];
        float v2 = src[(size_t)(c+2) * NQL] + bsm[c+2];
        float v3 = src[(size_t)(c+3) * NQL] + bsm[c+3];
        dst[(size_t)(c+0) * NQL] = __expf(v0 - m) * inv;
        dst[(size_t)(c+1) * NQL] = __expf(v1 - m) * inv;
        dst[(size_t)(c+2) * NQL] = __expf(v2 - m) * inv;
        dst[(size_t)(c+3) * NQL] = __expf(v3 - m) * inv;
    }
}

// ---------------- K6: output assembly (all c-contiguous, float4) ------------
__global__ __launch_bounds__(256) void assemble_kernel(
    const float* __restrict__ C, const float* __restrict__ At,
    const float* __restrict__ Bmt, float* __restrict__ out)
{
    size_t i = (size_t)blockIdx.x * 256 + threadIdx.x;   // float4 idx over B*D*CL/4
    size_t b = i >> 15;            // / 32768 (D*CL/4)
    size_t r = i & 32767;
    const float4* C4 = (const float4*)C;
    const float4* A4 = (const float4*)At;
    const float4* B4 = (const float4*)Bmt;
    float4* O4 = (float4*)out;

    float4 c  = C4[i];
    float4 a  = A4[i];
    float4 bm = B4[i];
    size_t o = b * 131072 + r;     // batch stride 4*D*CL/4
    O4[o]          = c;
    O4[o +  32768] = a;
    float4 p; p.x=c.x*a.x;  p.y=c.y*a.y;  p.z=c.z*a.z;  p.w=c.w*a.w;
    O4[o +  65536] = p;
    float4 g; g.x=c.x*bm.x; g.y=c.y*bm.y; g.z=c.z*bm.z; g.w=c.w*bm.w;
    O4[o +  98304] = g;
}

// ---------------- launch ----------------------------------------------------
extern "C" void kernel_launch(void* const* d_in, const int* in_sizes, int n_in,
                              void* d_out, int out_size)
{
    const float* C = (const float*)d_in[0];   // (B, D, CL)
    const float* Q = (const float*)d_in[1];   // (B, D, QL)
    const float* W = (const float*)d_in[2];   // (B*CL, 1, 3D)
    float* out = (float*)d_out;               // (B, 4D, CL)

    float *pAeff, *pbias, *pS, *pS1, *pS2, *pT, *pAt, *pBmt;
    cudaGetSymbolAddress((void**)&pAeff, g_Aeff);
    cudaGetSymbolAddress((void**)&pbias, g_bias);
    cudaGetSymbolAddress((void**)&pS,   g_S);
    cudaGetSymbolAddress((void**)&pS1,  g_S1);
    cudaGetSymbolAddress((void**)&pS2,  g_S2);
    cudaGetSymbolAddress((void**)&pT,   g_T);
    cudaGetSymbolAddress((void**)&pAt,  g_At);
    cudaGetSymbolAddress((void**)&pBmt, g_Bmt);

    // K0: Aeff + bias
    prep_kernel<<<dim3(NCL / 32, NB), 256>>>(C, W, pAeff, pbias);

    // K1: S = Aeff @ Q[b]   (M=CL, N=QL, K=D)
    gemm_tpl<128, 128, false><<<dim3(NQL / 128, NCL / 128, NB), 256>>>(
        pAeff, Q, pS, NCL, NQL, ND,
        (size_t)NCL * ND, (size_t)ND * NQL, (size_t)NCL * NQL);

    // K2a: S1 = row softmax(S)  (bias cancels along q)
    row_softmax_k<<<NB * NCL / 8, 256>>>(pS, pS1);

    // K2b: S2 = column softmax(S + bias[c])
    col_softmax_k<<<dim3(NQL / 64, NB), 64>>>(pS, pbias, pS2);

    // K3: A^T[d][c] = Q[b] @ S1^T   (M=D, N=CL, K=QL)
    gemm_tpl<128, 128, true><<<dim3(NCL / 128, 1, NB), 256>>>(
        Q, pS1, pAt, ND, NCL, NQL,
        (size_t)ND * NQL, (size_t)NCL * NQL, (size_t)ND * NCL);

    // K4: T[d][q] = C[b] @ S2      (M=D, N=QL, K=CL)  == S2tC^T
    gemm_tpl<128, 64, false><<<dim3(NQL / 64, 1, NB), 256>>>(
        C, pS2, pT, ND, NQL, NCL,
        (size_t)ND * NCL, (size_t)NCL * NQL, (size_t)ND * NQL);

    // K5: Bm^T[d][c] = T @ S1^T    (M=D, N=CL, K=QL)
    gemm_tpl<128, 128, true><<<dim3(NCL / 128, 1, NB), 256>>>(
        pT, pS1, pBmt, ND, NCL, NQL,
        (size_t)ND * NQL, (size_t)NCL * NQL, (size_t)ND * NCL);

    // K6: out = [C ; A^T ; C*A^T ; C*Bm^T]
    assemble_kernel<<<NB * ND * NCL / 4 / 256, 256>>>(C, pAt, pBmt, out);
}

// round 5
// speedup vs baseline: 1.3757x; 1.3757x over previous
#include <cuda_runtime.h>
#include <cstdint>

#define NB  32
#define ND  128
#define NCL 1024
#define NQL 512

// ---------------- scratch (device globals: allocation-free) ----------------
__device__ float g_Aeff[(size_t)NB * NCL * ND];     // Aeff[b][c][d]
__device__ float g_bias[(size_t)NB * NCL];          // bias[b][c]
__device__ float g_E2 [(size_t)NB * NCL * NQL];     // exp(S+bias)  [b][c][q]
__device__ float g_S1 [(size_t)NB * NCL * NQL];     // row softmax  [b][c][q]
__device__ float g_Lp [(size_t)NB * 8 * NQL];       // column partial sums
__device__ float g_invl[(size_t)NB * NQL];          // 1/column sum
__device__ float g_T  [(size_t)NB * ND * NQL];      // T[b][d][q] = S2tC^T
__device__ float g_At [(size_t)NB * ND * NCL];      // A^T[b][d][c]
__device__ float g_Bmt[(size_t)NB * ND * NCL];      // Bm^T[b][d][c]

// ---------------- K0: Aeff = wq + wqc*Ct ; bias = wc . Ct -------------------
__global__ __launch_bounds__(256) void prep_kernel(
    const float* __restrict__ C, const float* __restrict__ W,
    float* __restrict__ Aeff, float* __restrict__ bias)
{
    __shared__ float Csm[ND][33];
    const int b  = blockIdx.y;
    const int c0 = blockIdx.x * 32;
    const int t  = threadIdx.x;
    const float* Cb = C + (size_t)b * ND * NCL;

    #pragma unroll
    for (int i = 0; i < 16; i++) {
        int idx = i * 256 + t;
        int d = idx >> 5, c = idx & 31;
        Csm[d][c] = Cb[(size_t)d * NCL + c0 + c];
    }
    __syncthreads();

    #pragma unroll
    for (int i = 0; i < 16; i++) {
        int idx = i * 256 + t;
        int c = idx >> 7, d = idx & 127;
        size_t wb = (size_t)(b * NCL + c0 + c) * 384;
        float wq  = W[wb + d];
        float wqc = W[wb + 256 + d];
        Aeff[(size_t)(b * NCL + c0 + c) * ND + d] = wq + wqc * Csm[d][c];
    }

    int w = t >> 5, lane = t & 31;
    #pragma unroll
    for (int j = 0; j < 4; j++) {
        int c = w + j * 8;
        size_t wb = (size_t)(b * NCL + c0 + c) * 384 + 128;
        float s = 0.f;
        #pragma unroll
        for (int jj = 0; jj < 4; jj++) {
            int d = lane + jj * 32;
            s += W[wb + d] * Csm[d][c];
        }
        #pragma unroll
        for (int off = 16; off; off >>= 1)
            s += __shfl_xor_sync(0xffffffffu, s, off);
        if (lane == 0) bias[b * NCL + c0 + c] = s;
    }
}

// ---------------- batched tiled fp32 GEMM ----------------------------------
// EPI=0: plain C store.
// EPI=1: store exp(acc + bias[m]) instead of acc; also write deterministic
//        per-block column sums to xtra2 (Lpart). xtra1 = bias base.
// EPI=2: scale output column n by xtra1[b*N+n] (inv column sum).
template <int BM, int BN, bool TRANSB, int EPI>
__global__ __launch_bounds__(256) void gemm_tpl(
    const float* __restrict__ Aall, const float* __restrict__ Ball,
    float* __restrict__ Call,
    int M, int N, int K,
    size_t aStride, size_t bStride, size_t cStride,
    const float* __restrict__ xtra1, float* __restrict__ xtra2)
{
    constexpr int BK = 16;
    constexpr int TM = BM / 16, TN = BN / 16;
    constexpr int MG = TM / 4,  NG = TN / 4;
    constexpr int MSTEP = BM / MG, NSTEP = BN / NG;

    __shared__ float As[BK][BM + 4];
    __shared__ float Bs[BK][BN + 4];
    __shared__ float red[EPI == 1 ? 16 : 1][EPI == 1 ? BN + 1 : 1];

    const int b  = blockIdx.z;
    const int m0 = blockIdx.y * BM;
    const int n0 = blockIdx.x * BN;
    const float* A  = Aall + (size_t)b * aStride + (size_t)m0 * K;
    const float* Bp = Ball + (size_t)b * bStride;
    float*       Cm = Call + (size_t)b * cStride;

    const int tid = threadIdx.x;
    const int tx = tid & 15, ty = tid >> 4;

    float acc[TM][TN] = {};
    float ar[TM], br[TN];

    for (int k0 = 0; k0 < K; k0 += BK) {
        #pragma unroll
        for (int i = 0; i < (BM * 4) / 256; i++) {
            int lid = tid + i * 256;
            int r = lid >> 2, kq = lid & 3;
            float4 v = *(const float4*)(A + (size_t)r * K + k0 + kq * 4);
            As[kq * 4 + 0][r] = v.x; As[kq * 4 + 1][r] = v.y;
            As[kq * 4 + 2][r] = v.z; As[kq * 4 + 3][r] = v.w;
        }
        if (TRANSB) {
            #pragma unroll
            for (int i = 0; i < (BN * 4) / 256; i++) {
                int lid = tid + i * 256;
                int r = lid >> 2, kq = lid & 3;
                float4 v = *(const float4*)(Bp + (size_t)(n0 + r) * K + k0 + kq * 4);
                Bs[kq * 4 + 0][r] = v.x; Bs[kq * 4 + 1][r] = v.y;
                Bs[kq * 4 + 2][r] = v.z; Bs[kq * 4 + 3][r] = v.w;
            }
        } else {
            #pragma unroll
            for (int i = 0; i < (BK * BN / 4) / 256; i++) {
                int lid = tid + i * 256;
                int r = lid / (BN / 4), q = lid % (BN / 4);
                float4 v = *(const float4*)(Bp + (size_t)(k0 + r) * N + n0 + q * 4);
                *(float4*)&Bs[r][q * 4] = v;
            }
        }
        __syncthreads();

        #pragma unroll
        for (int k = 0; k < BK; k++) {
            #pragma unroll
            for (int g = 0; g < MG; g++) {
                float4 v = *(const float4*)&As[k][g * MSTEP + ty * 4];
                ar[g*4+0]=v.x; ar[g*4+1]=v.y; ar[g*4+2]=v.z; ar[g*4+3]=v.w;
            }
            #pragma unroll
            for (int g = 0; g < NG; g++) {
                float4 v = *(const float4*)&Bs[k][g * NSTEP + tx * 4];
                br[g*4+0]=v.x; br[g*4+1]=v.y; br[g*4+2]=v.z; br[g*4+3]=v.w;
            }
            #pragma unroll
            for (int mi = 0; mi < TM; mi++)
                #pragma unroll
                for (int ni = 0; ni < TN; ni++)
                    acc[mi][ni] = fmaf(ar[mi], br[ni], acc[mi][ni]);
        }
        __syncthreads();
    }

    if constexpr (EPI == 1) {
        // bias for this thread's 8 m rows
        float bvals[TM];
        #pragma unroll
        for (int mg = 0; mg < MG; mg++)
            #pragma unroll
            for (int i = 0; i < 4; i++)
                bvals[mg*4+i] = xtra1[(size_t)b * M + m0 + mg * MSTEP + ty * 4 + i];

        float qsum[TN] = {};
        #pragma unroll
        for (int mg = 0; mg < MG; mg++)
            #pragma unroll
            for (int i = 0; i < 4; i++) {
                int mi = mg * 4 + i;
                int m  = m0 + mg * MSTEP + ty * 4 + i;
                #pragma unroll
                for (int ng = 0; ng < NG; ng++) {
                    float4 v;
                    v.x = __expf(acc[mi][ng*4+0] + bvals[mi]);
                    v.y = __expf(acc[mi][ng*4+1] + bvals[mi]);
                    v.z = __expf(acc[mi][ng*4+2] + bvals[mi]);
                    v.w = __expf(acc[mi][ng*4+3] + bvals[mi]);
                    qsum[ng*4+0] += v.x; qsum[ng*4+1] += v.y;
                    qsum[ng*4+2] += v.z; qsum[ng*4+3] += v.w;
                    *(float4*)&Cm[(size_t)m * N + n0 + ng * NSTEP + tx * 4] = v;
                }
            }
        // deterministic per-block column reduction
        #pragma unroll
        for (int ng = 0; ng < NG; ng++)
            #pragma unroll
            for (int j = 0; j < 4; j++)
                red[ty][ng * NSTEP + tx * 4 + j] = qsum[ng*4+j];
        __syncthreads();
        if (tid < BN) {
            float s = 0.f;
            #pragma unroll
            for (int t = 0; t < 16; t++) s += red[t][tid];
            xtra2[((size_t)b * gridDim.y + blockIdx.y) * N + n0 + tid] = s;
        }
    } else {
        float sc[TN];
        if constexpr (EPI == 2) {
            #pragma unroll
            for (int ng = 0; ng < NG; ng++)
                #pragma unroll
                for (int j = 0; j < 4; j++)
                    sc[ng*4+j] = xtra1[(size_t)b * N + n0 + ng * NSTEP + tx * 4 + j];
        }
        #pragma unroll
        for (int mg = 0; mg < MG; mg++)
            #pragma unroll
            for (int i = 0; i < 4; i++) {
                int m = m0 + mg * MSTEP + ty * 4 + i;
                #pragma unroll
                for (int ng = 0; ng < NG; ng++) {
                    float4 v;
                    v.x = acc[mg*4+i][ng*4+0]; v.y = acc[mg*4+i][ng*4+1];
                    v.z = acc[mg*4+i][ng*4+2]; v.w = acc[mg*4+i][ng*4+3];
                    if constexpr (EPI == 2) {
                        v.x *= sc[ng*4+0]; v.y *= sc[ng*4+1];
                        v.z *= sc[ng*4+2]; v.w *= sc[ng*4+3];
                    }
                    *(float4*)&Cm[(size_t)m * N + n0 + ng * NSTEP + tx * 4] = v;
                }
            }
    }
}

// ---------------- combine: invl[b][q] = 1 / sum_y Lpart[b][y][q] ------------
__global__ __launch_bounds__(256) void combine_l_kernel(
    const float* __restrict__ Lp, float* __restrict__ invl)
{
    int i = blockIdx.x * 256 + threadIdx.x;    // b*NQL + q
    int b = i >> 9, q = i & 511;
    float s = 0.f;
    #pragma unroll
    for (int y = 0; y < 8; y++)
        s += Lp[((size_t)b * 8 + y) * NQL + q];
    invl[i] = 1.f / s;
}

// ---------------- row softmax from E2: S1 = E2 / rowsum(E2) -----------------
// (e^bias[c] factor cancels in the row normalization)
__global__ __launch_bounds__(256) void row_softmax_k(
    const float* __restrict__ E2, float* __restrict__ O)
{
    int row  = blockIdx.x * 8 + (threadIdx.x >> 5);
    int lane = threadIdx.x & 31;
    const float4* src = (const float4*)(E2 + (size_t)row * NQL);
    float4* dst = (float4*)(O + (size_t)row * NQL);

    float4 v[4];
    float s = 0.f;
    #pragma unroll
    for (int i = 0; i < 4; i++) {
        v[i] = src[lane + i * 32];
        s += v[i].x + v[i].y + v[i].z + v[i].w;
    }
    #pragma unroll
    for (int off = 16; off; off >>= 1)
        s += __shfl_xor_sync(0xffffffffu, s, off);
    float inv = 1.f / s;
    #pragma unroll
    for (int i = 0; i < 4; i++) {
        v[i].x *= inv; v[i].y *= inv; v[i].z *= inv; v[i].w *= inv;
        dst[lane + i * 32] = v[i];
    }
}

// ---------------- output assembly -------------------------------------------
__global__ __launch_bounds__(256) void assemble_kernel(
    const float* __restrict__ C, const float* __restrict__ At,
    const float* __restrict__ Bmt, float* __restrict__ out)
{
    size_t i = (size_t)blockIdx.x * 256 + threadIdx.x;
    size_t b = i >> 15;
    size_t r = i & 32767;
    const float4* C4 = (const float4*)C;
    const float4* A4 = (const float4*)At;
    const float4* B4 = (const float4*)Bmt;
    float4* O4 = (float4*)out;

    float4 c  = C4[i];
    float4 a  = A4[i];
    float4 bm = B4[i];
    size_t o = b * 131072 + r;
    O4[o]          = c;
    O4[o +  32768] = a;
    float4 p; p.x=c.x*a.x;  p.y=c.y*a.y;  p.z=c.z*a.z;  p.w=c.w*a.w;
    O4[o +  65536] = p;
    float4 g; g.x=c.x*bm.x; g.y=c.y*bm.y; g.z=c.z*bm.z; g.w=c.w*bm.w;
    O4[o +  98304] = g;
}

// ---------------- launch ----------------------------------------------------
extern "C" void kernel_launch(void* const* d_in, const int* in_sizes, int n_in,
                              void* d_out, int out_size)
{
    const float* C = (const float*)d_in[0];   // (B, D, CL)
    const float* Q = (const float*)d_in[1];   // (B, D, QL)
    const float* W = (const float*)d_in[2];   // (B*CL, 1, 3D)
    float* out = (float*)d_out;               // (B, 4D, CL)

    float *pAeff, *pbias, *pE2, *pS1, *pLp, *pinvl, *pT, *pAt, *pBmt;
    cudaGetSymbolAddress((void**)&pAeff, g_Aeff);
    cudaGetSymbolAddress((void**)&pbias, g_bias);
    cudaGetSymbolAddress((void**)&pE2,   g_E2);
    cudaGetSymbolAddress((void**)&pS1,   g_S1);
    cudaGetSymbolAddress((void**)&pLp,   g_Lp);
    cudaGetSymbolAddress((void**)&pinvl, g_invl);
    cudaGetSymbolAddress((void**)&pT,    g_T);
    cudaGetSymbolAddress((void**)&pAt,   g_At);
    cudaGetSymbolAddress((void**)&pBmt,  g_Bmt);

    // K0: Aeff + bias
    prep_kernel<<<dim3(NCL / 32, NB), 256>>>(C, W, pAeff, pbias);

    // K1: E2 = exp(Aeff @ Q + bias[c]); Lpart = per-block column sums
    gemm_tpl<128, 128, false, 1><<<dim3(NQL / 128, NCL / 128, NB), 256>>>(
        pAeff, Q, pE2, NCL, NQL, ND,
        (size_t)NCL * ND, (size_t)ND * NQL, (size_t)NCL * NQL, pbias, pLp);

    // combine partial column sums -> 1/l[q]
    combine_l_kernel<<<NB * NQL / 256, 256>>>(pLp, pinvl);

    // row softmax: S1 = E2 / rowsum(E2)
    row_softmax_k<<<NB * NCL / 8, 256>>>(pE2, pS1);

    // K3: A^T[d][c] = Q[b] @ S1^T   (M=D, N=CL, K=QL)
    gemm_tpl<128, 128, true, 0><<<dim3(NCL / 128, 1, NB), 256>>>(
        Q, pS1, pAt, ND, NCL, NQL,
        (size_t)ND * NQL, (size_t)NCL * NQL, (size_t)ND * NCL, nullptr, nullptr);

    // K4: T[d][q] = (C[b] @ E2) * invl[q]   (M=D, N=QL, K=CL)
    gemm_tpl<128, 64, false, 2><<<dim3(NQL / 64, 1, NB), 256>>>(
        C, pE2, pT, ND, NQL, NCL,
        (size_t)ND * NCL, (size_t)NCL * NQL, (size_t)ND * NQL, pinvl, nullptr);

    // K5: Bm^T[d][c] = T @ S1^T    (M=D, N=CL, K=QL)
    gemm_tpl<128, 128, true, 0><<<dim3(NCL / 128, 1, NB), 256>>>(
        pT, pS1, pBmt, ND, NCL, NQL,
        (size_t)ND * NQL, (size_t)NCL * NQL, (size_t)ND * NCL, nullptr, nullptr);

    // K6: out = [C ; A^T ; C*A^T ; C*Bm^T]
    assemble_kernel<<<NB * ND * NCL / 4 / 256, 256>>>(C, pAt, pBmt, out);
}

// round 6
// speedup vs baseline: 2.3166x; 1.6840x over previous
#include <cuda_runtime.h>
#include <cstdint>

#define NB  32
#define ND  128
#define NCL 1024
#define NQL 512

// ---------------- scratch (device globals: allocation-free) ----------------
__device__ float g_Aeff[(size_t)NB * NCL * ND];     // Aeff[b][c][d]
__device__ float g_bias[(size_t)NB * NCL];          // bias[b][c]
__device__ float g_E2 [(size_t)NB * NCL * NQL];     // exp(S+bias)  [b][c][q]
__device__ float g_Lp [(size_t)NB * 8 * NQL];       // column partial sums (8 = NCL/128)
__device__ float g_Rp [(size_t)NB * 4 * NCL];       // row partial sums    (4 = NQL/128)
__device__ float g_invl[(size_t)NB * NQL];          // 1 / column sum
__device__ float g_rinv[(size_t)NB * NCL];          // 1 / row sum
__device__ float g_T  [(size_t)NB * ND * NQL];      // T[b][d][q] = S2tC^T
__device__ float g_At [(size_t)NB * ND * NCL];      // A^T[b][d][c]
__device__ float g_Bmt[(size_t)NB * ND * NCL];      // Bm^T[b][d][c]

// ---------------- helpers ---------------------------------------------------
__device__ __forceinline__ uint32_t f2tf(float x) {
    uint32_t r; asm("cvt.rna.tf32.f32 %0, %1;" : "=r"(r) : "f"(x)); return r;
}
__device__ __forceinline__ void mma8(float* d, const uint32_t* a, const uint32_t* b) {
    asm("mma.sync.aligned.m16n8k8.row.col.f32.tf32.tf32.f32 "
        "{%0,%1,%2,%3}, {%4,%5,%6,%7}, {%8,%9}, {%0,%1,%2,%3};"
        : "+f"(d[0]), "+f"(d[1]), "+f"(d[2]), "+f"(d[3])
        : "r"(a[0]), "r"(a[1]), "r"(a[2]), "r"(a[3]), "r"(b[0]), "r"(b[1]));
}

// ---------------- K0: Aeff = wq + wqc*Ct ; bias = wc . Ct -------------------
__global__ __launch_bounds__(256) void prep_kernel(
    const float* __restrict__ C, const float* __restrict__ W,
    float* __restrict__ Aeff, float* __restrict__ bias)
{
    __shared__ float Csm[ND][33];
    const int b  = blockIdx.y;
    const int c0 = blockIdx.x * 32;
    const int t  = threadIdx.x;
    const float* Cb = C + (size_t)b * ND * NCL;

    #pragma unroll
    for (int i = 0; i < 16; i++) {
        int idx = i * 256 + t;
        int d = idx >> 5, c = idx & 31;
        Csm[d][c] = Cb[(size_t)d * NCL + c0 + c];
    }
    __syncthreads();

    #pragma unroll
    for (int i = 0; i < 16; i++) {
        int idx = i * 256 + t;
        int c = idx >> 7, d = idx & 127;
        size_t wb = (size_t)(b * NCL + c0 + c) * 384;
        float wq  = W[wb + d];
        float wqc = W[wb + 256 + d];
        Aeff[(size_t)(b * NCL + c0 + c) * ND + d] = wq + wqc * Csm[d][c];
    }

    int w = t >> 5, lane = t & 31;
    #pragma unroll
    for (int j = 0; j < 4; j++) {
        int c = w + j * 8;
        size_t wb = (size_t)(b * NCL + c0 + c) * 384 + 128;
        float s = 0.f;
        #pragma unroll
        for (int jj = 0; jj < 4; jj++) {
            int d = lane + jj * 32;
            s += W[wb + d] * Csm[d][c];
        }
        #pragma unroll
        for (int off = 16; off; off >>= 1)
            s += __shfl_xor_sync(0xffffffffu, s, off);
        if (lane == 0) bias[b * NCL + c0 + c] = s;
    }
}

// ---------------- tensor-core tf32 batched GEMM ------------------------------
// Cout[M x N] = A[M x K rm] @ B (B: K x N rm if !TRANSB, else N x K rm).
// Block tile 128x128, BK=16, 8 warps as 2(m) x 4(n), warp tile 64x32 of
// m16n8k8 tf32 atoms.
// EPI=0: plain store.
// EPI=1: store exp(acc + bias[m]); deterministic per-block column partial sums
//        -> colpart[(b*gridDim.y+by)*N + n]  and row partial sums
//        -> rowpart[(b*gridDim.x+bx)*M + m].  xtra1 = bias.
// EPI=2: scale output column n by xtra1[b*N + n].
template <bool TRANSB, int EPI>
__global__ __launch_bounds__(256) void mma_gemm(
    const float* __restrict__ Aall, const float* __restrict__ Ball,
    float* __restrict__ Call,
    int M, int N, int K,
    size_t aStride, size_t bStride, size_t cStride,
    const float* __restrict__ xtra1,
    float* __restrict__ colpart, float* __restrict__ rowpart)
{
    constexpr int BM = 128, BN = 128, BK = 16;
    __shared__ uint32_t As[BK][BM + 8];
    __shared__ uint32_t Bs[BK][BN + 8];
    __shared__ float red_c[2][BN];   // EPI=1 column partials per m-warp-row
    __shared__ float red_r[4][BM];   // EPI=1 row partials per n-warp-col

    const int b  = blockIdx.z;
    const int m0 = blockIdx.y * BM;
    const int n0 = blockIdx.x * BN;
    const float* A  = Aall + (size_t)b * aStride + (size_t)m0 * K;
    const float* Bp = Ball + (size_t)b * bStride;
    float*       Cm = Call + (size_t)b * cStride;

    const int tid  = threadIdx.x;
    const int w    = tid >> 5;
    const int lane = tid & 31;
    const int g    = lane >> 2;      // groupID
    const int t    = lane & 3;       // thread-in-group
    const int wm   = (w >> 2) * 64;  // warp m offset (2 rows of warps)
    const int wn   = (w & 3) * 32;   // warp n offset (4 cols of warps)

    float acc[4][4][4];
    #pragma unroll
    for (int i = 0; i < 4; i++)
        #pragma unroll
        for (int j = 0; j < 4; j++)
            #pragma unroll
            for (int r = 0; r < 4; r++) acc[i][j][r] = 0.f;

    for (int k0 = 0; k0 < K; k0 += BK) {
        // A tile: 128 rows x 16 k, float4 along k, tf32-convert, store [k][m]
        #pragma unroll
        for (int i = 0; i < 2; i++) {
            int lid = tid + i * 256;
            int r = lid >> 2, kq = lid & 3;
            float4 v = *(const float4*)(A + (size_t)r * K + k0 + kq * 4);
            As[kq * 4 + 0][r] = f2tf(v.x); As[kq * 4 + 1][r] = f2tf(v.y);
            As[kq * 4 + 2][r] = f2tf(v.z); As[kq * 4 + 3][r] = f2tf(v.w);
        }
        if (TRANSB) {
            #pragma unroll
            for (int i = 0; i < 2; i++) {
                int lid = tid + i * 256;
                int r = lid >> 2, kq = lid & 3;
                float4 v = *(const float4*)(Bp + (size_t)(n0 + r) * K + k0 + kq * 4);
                Bs[kq * 4 + 0][r] = f2tf(v.x); Bs[kq * 4 + 1][r] = f2tf(v.y);
                Bs[kq * 4 + 2][r] = f2tf(v.z); Bs[kq * 4 + 3][r] = f2tf(v.w);
            }
        } else {
            #pragma unroll
            for (int i = 0; i < 2; i++) {
                int lid = tid + i * 256;
                int r = lid >> 5, q = lid & 31;
                float4 v = *(const float4*)(Bp + (size_t)(k0 + r) * N + n0 + q * 4);
                uint4 u;
                u.x = f2tf(v.x); u.y = f2tf(v.y); u.z = f2tf(v.z); u.w = f2tf(v.w);
                *(uint4*)&Bs[r][q * 4] = u;
            }
        }
        __syncthreads();

        #pragma unroll
        for (int ks = 0; ks < 2; ks++) {
            const int kb = ks * 8;
            uint32_t af[4][4], bf[4][2];
            #pragma unroll
            for (int im = 0; im < 4; im++) {
                int mrow = wm + im * 16 + g;
                af[im][0] = As[kb + t    ][mrow];
                af[im][1] = As[kb + t    ][mrow + 8];
                af[im][2] = As[kb + t + 4][mrow];
                af[im][3] = As[kb + t + 4][mrow + 8];
            }
            #pragma unroll
            for (int in = 0; in < 4; in++) {
                int ncol = wn + in * 8 + g;
                bf[in][0] = Bs[kb + t    ][ncol];
                bf[in][1] = Bs[kb + t + 4][ncol];
            }
            #pragma unroll
            for (int im = 0; im < 4; im++)
                #pragma unroll
                for (int in = 0; in < 4; in++)
                    mma8(acc[im][in], af[im], bf[in]);
        }
        __syncthreads();
    }

    // ---------------- epilogue ----------------
    if constexpr (EPI == 1) {
        float bias_r[4][2];
        #pragma unroll
        for (int im = 0; im < 4; im++)
            #pragma unroll
            for (int h = 0; h < 2; h++)
                bias_r[im][h] = xtra1[(size_t)b * M + m0 + wm + im * 16 + g + 8 * h];

        float qs[4][2];   // per (n-atom, j) column partials (over this thread's 8 rows)
        float rs[4][2];   // per (m-atom, h) row partials    (over this thread's 8 cols)
        #pragma unroll
        for (int i = 0; i < 4; i++)
            #pragma unroll
            for (int j = 0; j < 2; j++) { qs[i][j] = 0.f; rs[i][j] = 0.f; }

        #pragma unroll
        for (int im = 0; im < 4; im++)
            #pragma unroll
            for (int h = 0; h < 2; h++) {
                int m = m0 + wm + im * 16 + g + 8 * h;
                #pragma unroll
                for (int in = 0; in < 4; in++) {
                    float e0 = __expf(acc[im][in][2 * h]     + bias_r[im][h]);
                    float e1 = __expf(acc[im][in][2 * h + 1] + bias_r[im][h]);
                    float2 v; v.x = e0; v.y = e1;
                    *(float2*)&Cm[(size_t)m * N + n0 + wn + in * 8 + 2 * t] = v;
                    qs[in][0] += e0; qs[in][1] += e1;
                    rs[im][h] += e0 + e1;
                }
            }
        // column reduce over g (lanes differ in bits 2..4)
        #pragma unroll
        for (int in = 0; in < 4; in++)
            #pragma unroll
            for (int j = 0; j < 2; j++) {
                float s = qs[in][j];
                s += __shfl_xor_sync(0xffffffffu, s, 16);
                s += __shfl_xor_sync(0xffffffffu, s, 8);
                s += __shfl_xor_sync(0xffffffffu, s, 4);
                if (g == 0) red_c[w >> 2][wn + in * 8 + 2 * t + j] = s;
            }
        // row reduce over t (lanes differ in bits 0..1)
        #pragma unroll
        for (int im = 0; im < 4; im++)
            #pragma unroll
            for (int h = 0; h < 2; h++) {
                float s = rs[im][h];
                s += __shfl_xor_sync(0xffffffffu, s, 1);
                s += __shfl_xor_sync(0xffffffffu, s, 2);
                if (t == 0) red_r[w & 3][wm + im * 16 + g + 8 * h] = s;
            }
        __syncthreads();
        if (tid < 128) {
            colpart[((size_t)b * gridDim.y + blockIdx.y) * N + n0 + tid] =
                red_c[0][tid] + red_c[1][tid];
        } else {
            int m = tid - 128;
            rowpart[((size_t)b * gridDim.x + blockIdx.x) * M + m0 + m] =
                red_r[0][m] + red_r[1][m] + red_r[2][m] + red_r[3][m];
        }
    } else {
        float sc[4][2];
        if constexpr (EPI == 2) {
            #pragma unroll
            for (int in = 0; in < 4; in++)
                #pragma unroll
                for (int j = 0; j < 2; j++)
                    sc[in][j] = xtra1[(size_t)b * N + n0 + wn + in * 8 + 2 * t + j];
        }
        #pragma unroll
        for (int im = 0; im < 4; im++)
            #pragma unroll
            for (int h = 0; h < 2; h++) {
                int m = m0 + wm + im * 16 + g + 8 * h;
                #pragma unroll
                for (int in = 0; in < 4; in++) {
                    float2 v;
                    v.x = acc[im][in][2 * h];
                    v.y = acc[im][in][2 * h + 1];
                    if constexpr (EPI == 2) { v.x *= sc[in][0]; v.y *= sc[in][1]; }
                    *(float2*)&Cm[(size_t)m * N + n0 + wn + in * 8 + 2 * t] = v;
                }
            }
    }
}

// ---------------- combine partial sums -> invl (per q), rinv (per c) --------
__global__ __launch_bounds__(256) void combine_k(
    const float* __restrict__ Lp, const float* __restrict__ Rp,
    float* __restrict__ invl, float* __restrict__ rinv)
{
    int i = blockIdx.x * 256 + threadIdx.x;
    const int nbq = NB * NQL;
    if (i < nbq) {
        int b = i >> 9, q = i & 511;
        float s = 0.f;
        #pragma unroll
        for (int y = 0; y < 8; y++) s += Lp[((size_t)b * 8 + y) * NQL + q];
        invl[i] = 1.f / s;
    } else {
        int j = i - nbq;
        int b = j >> 10, c = j & 1023;
        float s = 0.f;
        #pragma unroll
        for (int x = 0; x < 4; x++) s += Rp[((size_t)b * 4 + x) * NCL + c];
        rinv[j] = 1.f / s;
    }
}

// ---------------- output assembly -------------------------------------------
__global__ __launch_bounds__(256) void assemble_kernel(
    const float* __restrict__ C, const float* __restrict__ At,
    const float* __restrict__ Bmt, float* __restrict__ out)
{
    size_t i = (size_t)blockIdx.x * 256 + threadIdx.x;
    size_t b = i >> 15;
    size_t r = i & 32767;
    const float4* C4 = (const float4*)C;
    const float4* A4 = (const float4*)At;
    const float4* B4 = (const float4*)Bmt;
    float4* O4 = (float4*)out;

    float4 c  = C4[i];
    float4 a  = A4[i];
    float4 bm = B4[i];
    size_t o = b * 131072 + r;
    O4[o]          = c;
    O4[o +  32768] = a;
    float4 p; p.x=c.x*a.x;  p.y=c.y*a.y;  p.z=c.z*a.z;  p.w=c.w*a.w;
    O4[o +  65536] = p;
    float4 g; g.x=c.x*bm.x; g.y=c.y*bm.y; g.z=c.z*bm.z; g.w=c.w*bm.w;
    O4[o +  98304] = g;
}

// ---------------- launch ----------------------------------------------------
extern "C" void kernel_launch(void* const* d_in, const int* in_sizes, int n_in,
                              void* d_out, int out_size)
{
    const float* C = (const float*)d_in[0];   // (B, D, CL)
    const float* Q = (const float*)d_in[1];   // (B, D, QL)
    const float* W = (const float*)d_in[2];   // (B*CL, 1, 3D)
    float* out = (float*)d_out;               // (B, 4D, CL)

    float *pAeff, *pbias, *pE2, *pLp, *pRp, *pinvl, *prinv, *pT, *pAt, *pBmt;
    cudaGetSymbolAddress((void**)&pAeff, g_Aeff);
    cudaGetSymbolAddress((void**)&pbias, g_bias);
    cudaGetSymbolAddress((void**)&pE2,   g_E2);
    cudaGetSymbolAddress((void**)&pLp,   g_Lp);
    cudaGetSymbolAddress((void**)&pRp,   g_Rp);
    cudaGetSymbolAddress((void**)&pinvl, g_invl);
    cudaGetSymbolAddress((void**)&prinv, g_rinv);
    cudaGetSymbolAddress((void**)&pT,    g_T);
    cudaGetSymbolAddress((void**)&pAt,   g_At);
    cudaGetSymbolAddress((void**)&pBmt,  g_Bmt);

    // K0: Aeff + bias
    prep_kernel<<<dim3(NCL / 32, NB), 256>>>(C, W, pAeff, pbias);

    // K1: E2 = exp(Aeff @ Q + bias[c]); column+row partial sums
    mma_gemm<false, 1><<<dim3(NQL / 128, NCL / 128, NB), 256>>>(
        pAeff, Q, pE2, NCL, NQL, ND,
        (size_t)NCL * ND, (size_t)ND * NQL, (size_t)NCL * NQL,
        pbias, pLp, pRp);

    // combine -> invl[b][q], rinv[b][c]
    combine_k<<<NB * (NQL + NCL) / 256, 256>>>(pLp, pRp, pinvl, prinv);

    // K3: A^T[d][c] = rinv[c] * (Q @ E2^T)   (M=D, N=CL, K=QL)
    mma_gemm<true, 2><<<dim3(NCL / 128, 1, NB), 256>>>(
        Q, pE2, pAt, ND, NCL, NQL,
        (size_t)ND * NQL, (size_t)NCL * NQL, (size_t)ND * NCL,
        prinv, nullptr, nullptr);

    // K4: T[d][q] = invl[q] * (C @ E2)       (M=D, N=QL, K=CL)
    mma_gemm<false, 2><<<dim3(NQL / 128, 1, NB), 256>>>(
        C, pE2, pT, ND, NQL, NCL,
        (size_t)ND * NCL, (size_t)NCL * NQL, (size_t)ND * NQL,
        pinvl, nullptr, nullptr);

    // K5: Bm^T[d][c] = rinv[c] * (T @ E2^T)  (M=D, N=CL, K=QL)
    mma_gemm<true, 2><<<dim3(NCL / 128, 1, NB), 256>>>(
        pT, pE2, pBmt, ND, NCL, NQL,
        (size_t)ND * NQL, (size_t)NCL * NQL, (size_t)ND * NCL,
        prinv, nullptr, nullptr);

    // K6: out = [C ; A^T ; C*A^T ; C*Bm^T]
    assemble_kernel<<<NB * ND * NCL / 4 / 256, 256>>>(C, pAt, pBmt, out);
}

// round 7
// speedup vs baseline: 2.6351x; 1.1375x over previous
#include <cuda_runtime.h>
#include <cstdint>

#define NB  32
#define ND  128
#define NCL 1024
#define NQL 512

// ---------------- scratch (device globals: allocation-free) ----------------
__device__ float g_Aeff[(size_t)NB * NCL * ND];     // Aeff[b][c][d]
__device__ float g_bias[(size_t)NB * NCL];          // bias[b][c]
__device__ float g_E2 [(size_t)NB * NCL * NQL];     // exp(S+bias)  [b][c][q]
__device__ float g_Lp [(size_t)NB * 8 * NQL];       // column partial sums
__device__ float g_Rp [(size_t)NB * 4 * NCL];       // row partial sums
__device__ float g_invl[(size_t)NB * NQL];          // 1 / column sum
__device__ float g_rinv[(size_t)NB * NCL];          // 1 / row sum
__device__ float g_T  [(size_t)NB * ND * NQL];      // T[b][d][q] = S2tC^T
__device__ float g_At [(size_t)NB * ND * NCL];      // A^T[b][d][c]
__device__ float g_Bmt[(size_t)NB * ND * NCL];      // Bm^T[b][d][c]

// ---------------- helpers ---------------------------------------------------
__device__ __forceinline__ uint32_t f2tf(float x) {
    uint32_t r; asm("cvt.rna.tf32.f32 %0, %1;" : "=r"(r) : "f"(x)); return r;
}
__device__ __forceinline__ void mma8(float* d, const uint32_t* a, const uint32_t* b) {
    asm("mma.sync.aligned.m16n8k8.row.col.f32.tf32.tf32.f32 "
        "{%0,%1,%2,%3}, {%4,%5,%6,%7}, {%8,%9}, {%0,%1,%2,%3};"
        : "+f"(d[0]), "+f"(d[1]), "+f"(d[2]), "+f"(d[3])
        : "r"(a[0]), "r"(a[1]), "r"(a[2]), "r"(a[3]), "r"(b[0]), "r"(b[1]));
}

// ---------------- K0: Aeff = wq + wqc*Ct ; bias = wc . Ct -------------------
__global__ __launch_bounds__(256) void prep_kernel(
    const float* __restrict__ C, const float* __restrict__ W,
    float* __restrict__ Aeff, float* __restrict__ bias)
{
    __shared__ float Csm[ND][33];
    const int b  = blockIdx.y;
    const int c0 = blockIdx.x * 32;
    const int t  = threadIdx.x;
    const float* Cb = C + (size_t)b * ND * NCL;

    #pragma unroll
    for (int i = 0; i < 16; i++) {
        int idx = i * 256 + t;
        int d = idx >> 5, c = idx & 31;
        Csm[d][c] = Cb[(size_t)d * NCL + c0 + c];
    }
    __syncthreads();

    #pragma unroll
    for (int i = 0; i < 16; i++) {
        int idx = i * 256 + t;
        int c = idx >> 7, d = idx & 127;
        size_t wb = (size_t)(b * NCL + c0 + c) * 384;
        float wq  = W[wb + d];
        float wqc = W[wb + 256 + d];
        Aeff[(size_t)(b * NCL + c0 + c) * ND + d] = wq + wqc * Csm[d][c];
    }

    int w = t >> 5, lane = t & 31;
    #pragma unroll
    for (int j = 0; j < 4; j++) {
        int c = w + j * 8;
        size_t wb = (size_t)(b * NCL + c0 + c) * 384 + 128;
        float s = 0.f;
        #pragma unroll
        for (int jj = 0; jj < 4; jj++) {
            int d = lane + jj * 32;
            s += W[wb + d] * Csm[d][c];
        }
        #pragma unroll
        for (int off = 16; off; off >>= 1)
            s += __shfl_xor_sync(0xffffffffu, s, off);
        if (lane == 0) bias[b * NCL + c0 + c] = s;
    }
}

// ---------------- tensor-core tf32 batched GEMM (fragment smem layout) ------
// Cout[M x N] = A[M x K rm] @ B (B: K x N rm if !TRANSB, else N x K rm).
// Block tile 128 x BN, BK=16, 8 warps as 2(m) x 4(n).
// Smem stores tiles directly as per-lane MMA fragments:
//   Asf[ks][m_atom][lane][4]   (lane t-bits XOR-swizzled by (g>>1)&3)
//   Bsf[ks][n_atom][lane*2+reg] with atom stride 66 words (padding vs 64)
// EPI=0 plain store; EPI=1 exp(acc+bias[m]) + col/row partial sums;
// EPI=2 scale column n by xtra1[b*N+n].
template <bool TRANSB, int EPI, int BN>
__global__ __launch_bounds__(256, 2) void mma_gemm(
    const float* __restrict__ Aall, const float* __restrict__ Ball,
    float* __restrict__ Call,
    int M, int N, int K,
    size_t aStride, size_t bStride, size_t cStride,
    const float* __restrict__ xtra1,
    float* __restrict__ colpart, float* __restrict__ rowpart)
{
    constexpr int BM = 128, BK = 16;
    constexpr int NB8 = BN / 8;       // n-atoms per block
    constexpr int NI  = BN / 32;      // n-atoms per warp
    constexpr int BLD = BN / 64;      // B float4 loads per thread

    __shared__ uint32_t Asf[2 * 8 * 128];       // [ks][im][lane][reg]
    __shared__ uint32_t Bsf[2 * NB8 * 66];      // [ks][in][lane*2+reg], padded
    __shared__ float red_c[EPI == 1 ? 2 : 1][EPI == 1 ? BN : 1];
    __shared__ float red_r[EPI == 1 ? 4 : 1][EPI == 1 ? BM : 1];

    const int b  = blockIdx.z;
    const int m0 = blockIdx.y * BM;
    const int n0 = blockIdx.x * BN;
    const float* A  = Aall + (size_t)b * aStride + (size_t)m0 * K;
    const float* Bp = Ball + (size_t)b * bStride;
    float*       Cm = Call + (size_t)b * cStride;

    const int tid  = threadIdx.x;
    const int w    = tid >> 5;
    const int lane = tid & 31;
    const int g    = lane >> 2;
    const int t    = lane & 3;
    const int ma0  = (w >> 2) * 4;          // m-atom base for this warp
    const int na0  = (w & 3) * NI;          // n-atom base
    const int wm   = (w >> 2) * 64;
    const int wn   = (w & 3) * (8 * NI);
    const int swa  = lane ^ ((lane >> 3) & 3);   // A-frag load slot

    // ---- A loader precompute (2 float4 per thread) ----
    const float* pA[2];
    int aBase[2], aSwz[2];
    #pragma unroll
    for (int i = 0; i < 2; i++) {
        int lid = tid + i * 256;
        int r = lid >> 2, kq = lid & 3;
        pA[i] = A + (size_t)r * K + kq * 4;
        int im = r >> 4, gg = r & 7, h = (r >> 3) & 1;
        int ks = kq >> 1, reg = h + 2 * (kq & 1);
        aBase[i] = (ks * 8 + im) * 128 + gg * 16 + reg;
        aSwz[i]  = (gg >> 1) & 3;
    }
    // ---- B loader precompute ----
    const float* pB[BLD];
    int bBase[BLD], bStepJ;
    if (TRANSB) {
        bStepJ = 2;
        #pragma unroll
        for (int i = 0; i < BLD; i++) {
            int lid = tid + i * 256;
            int r = lid >> 2, kq = lid & 3;
            pB[i] = Bp + (size_t)(n0 + r) * K + kq * 4;
            int in = r >> 3, gg = r & 7;
            int ks = kq >> 1, reg = kq & 1;
            bBase[i] = (ks * NB8 + in) * 66 + gg * 8 + reg;
        }
    } else {
        bStepJ = 8;
        #pragma unroll
        for (int i = 0; i < BLD; i++) {
            int lid = tid + i * 256;
            int r, q;
            if (BN == 128) { r = lid >> 5; q = lid & 31; }
            else           { r = lid >> 4; q = lid & 15; }
            pB[i] = Bp + (size_t)r * N + n0 + q * 4;
            int ks = r >> 3, kk = r & 7, tt = kk & 3, reg = kk >> 2;
            bBase[i] = (ks * NB8 + (q >> 1)) * 66 + (q & 1) * 32 + tt * 2 + reg;
        }
    }

    float acc[4][NI][4];
    #pragma unroll
    for (int i = 0; i < 4; i++)
        #pragma unroll
        for (int j = 0; j < NI; j++)
            #pragma unroll
            for (int r = 0; r < 4; r++) acc[i][j][r] = 0.f;

    // ---- prologue global loads ----
    float4 aR[2], bR[BLD];
    #pragma unroll
    for (int i = 0; i < 2; i++) aR[i] = *(const float4*)pA[i];
    #pragma unroll
    for (int i = 0; i < BLD; i++) bR[i] = *(const float4*)pB[i];

    for (int k0 = 0; k0 < K; k0 += BK) {
        // store prefetched regs -> fragment smem
        #pragma unroll
        for (int i = 0; i < 2; i++) {
            float v[4] = {aR[i].x, aR[i].y, aR[i].z, aR[i].w};
            #pragma unroll
            for (int j = 0; j < 4; j++)
                Asf[aBase[i] + ((j ^ aSwz[i]) << 2)] = f2tf(v[j]);
        }
        #pragma unroll
        for (int i = 0; i < BLD; i++) {
            float v[4] = {bR[i].x, bR[i].y, bR[i].z, bR[i].w};
            #pragma unroll
            for (int j = 0; j < 4; j++)
                Bsf[bBase[i] + j * bStepJ] = f2tf(v[j]);
        }
        __syncthreads();

        if (k0 + BK < K) {
            #pragma unroll
            for (int i = 0; i < 2; i++) { pA[i] += BK; aR[i] = *(const float4*)pA[i]; }
            #pragma unroll
            for (int i = 0; i < BLD; i++) {
                pB[i] += TRANSB ? BK : (size_t)BK * N;
                bR[i] = *(const float4*)pB[i];
            }
        }

        #pragma unroll
        for (int ks = 0; ks < 2; ks++) {
            uint4 af[4];
            uint2 bf[NI];
            const uint32_t* ab = &Asf[(ks * 8 + ma0) * 128 + swa * 4];
            #pragma unroll
            for (int im = 0; im < 4; im++)
                af[im] = *(const uint4*)(ab + im * 128);
            const uint32_t* bb = &Bsf[(ks * NB8 + na0) * 66 + lane * 2];
            #pragma unroll
            for (int in = 0; in < NI; in++)
                bf[in] = *(const uint2*)(bb + in * 66);
            #pragma unroll
            for (int im = 0; im < 4; im++)
                #pragma unroll
                for (int in = 0; in < NI; in++)
                    mma8(acc[im][in], (const uint32_t*)&af[im], (const uint32_t*)&bf[in]);
        }
        __syncthreads();
    }

    // ---------------- epilogue ----------------
    if constexpr (EPI == 1) {
        float bias_r[4][2];
        #pragma unroll
        for (int im = 0; im < 4; im++)
            #pragma unroll
            for (int h = 0; h < 2; h++)
                bias_r[im][h] = xtra1[(size_t)b * M + m0 + wm + im * 16 + g + 8 * h];

        float qs[NI][2];
        float rs[4][2];
        #pragma unroll
        for (int i = 0; i < NI; i++) { qs[i][0] = 0.f; qs[i][1] = 0.f; }
        #pragma unroll
        for (int i = 0; i < 4; i++)  { rs[i][0] = 0.f; rs[i][1] = 0.f; }

        #pragma unroll
        for (int im = 0; im < 4; im++)
            #pragma unroll
            for (int h = 0; h < 2; h++) {
                int m = m0 + wm + im * 16 + g + 8 * h;
                #pragma unroll
                for (int in = 0; in < NI; in++) {
                    float e0 = __expf(acc[im][in][2 * h]     + bias_r[im][h]);
                    float e1 = __expf(acc[im][in][2 * h + 1] + bias_r[im][h]);
                    float2 v; v.x = e0; v.y = e1;
                    *(float2*)&Cm[(size_t)m * N + n0 + wn + in * 8 + 2 * t] = v;
                    qs[in][0] += e0; qs[in][1] += e1;
                    rs[im][h] += e0 + e1;
                }
            }
        #pragma unroll
        for (int in = 0; in < NI; in++)
            #pragma unroll
            for (int j = 0; j < 2; j++) {
                float s = qs[in][j];
                s += __shfl_xor_sync(0xffffffffu, s, 16);
                s += __shfl_xor_sync(0xffffffffu, s, 8);
                s += __shfl_xor_sync(0xffffffffu, s, 4);
                if (g == 0) red_c[w >> 2][wn + in * 8 + 2 * t + j] = s;
            }
        #pragma unroll
        for (int im = 0; im < 4; im++)
            #pragma unroll
            for (int h = 0; h < 2; h++) {
                float s = rs[im][h];
                s += __shfl_xor_sync(0xffffffffu, s, 1);
                s += __shfl_xor_sync(0xffffffffu, s, 2);
                if (t == 0) red_r[w & 3][wm + im * 16 + g + 8 * h] = s;
            }
        __syncthreads();
        if (tid < BN) {
            colpart[((size_t)b * gridDim.y + blockIdx.y) * N + n0 + tid] =
                red_c[0][tid] + red_c[1][tid];
        } else if (tid < BN + BM) {
            int m = tid - BN;
            rowpart[((size_t)b * gridDim.x + blockIdx.x) * M + m0 + m] =
                red_r[0][m] + red_r[1][m] + red_r[2][m] + red_r[3][m];
        }
    } else {
        float sc[NI][2];
        if constexpr (EPI == 2) {
            #pragma unroll
            for (int in = 0; in < NI; in++)
                #pragma unroll
                for (int j = 0; j < 2; j++)
                    sc[in][j] = xtra1[(size_t)b * N + n0 + wn + in * 8 + 2 * t + j];
        }
        #pragma unroll
        for (int im = 0; im < 4; im++)
            #pragma unroll
            for (int h = 0; h < 2; h++) {
                int m = m0 + wm + im * 16 + g + 8 * h;
                #pragma unroll
                for (int in = 0; in < NI; in++) {
                    float2 v;
                    v.x = acc[im][in][2 * h];
                    v.y = acc[im][in][2 * h + 1];
                    if constexpr (EPI == 2) { v.x *= sc[in][0]; v.y *= sc[in][1]; }
                    *(float2*)&Cm[(size_t)m * N + n0 + wn + in * 8 + 2 * t] = v;
                }
            }
    }
}

// ---------------- combine partial sums -> invl (per q), rinv (per c) --------
__global__ __launch_bounds__(256) void combine_k(
    const float* __restrict__ Lp, const float* __restrict__ Rp,
    float* __restrict__ invl, float* __restrict__ rinv)
{
    int i = blockIdx.x * 256 + threadIdx.x;
    const int nbq = NB * NQL;
    if (i < nbq) {
        int b = i >> 9, q = i & 511;
        float s = 0.f;
        #pragma unroll
        for (int y = 0; y < 8; y++) s += Lp[((size_t)b * 8 + y) * NQL + q];
        invl[i] = 1.f / s;
    } else {
        int j = i - nbq;
        int b = j >> 10, c = j & 1023;
        float s = 0.f;
        #pragma unroll
        for (int x = 0; x < 4; x++) s += Rp[((size_t)b * 4 + x) * NCL + c];
        rinv[j] = 1.f / s;
    }
}

// ---------------- output assembly -------------------------------------------
__global__ __launch_bounds__(256) void assemble_kernel(
    const float* __restrict__ C, const float* __restrict__ At,
    const float* __restrict__ Bmt, float* __restrict__ out)
{
    size_t i = (size_t)blockIdx.x * 256 + threadIdx.x;
    size_t b = i >> 15;
    size_t r = i & 32767;
    const float4* C4 = (const float4*)C;
    const float4* A4 = (const float4*)At;
    const float4* B4 = (const float4*)Bmt;
    float4* O4 = (float4*)out;

    float4 c  = C4[i];
    float4 a  = A4[i];
    float4 bm = B4[i];
    size_t o = b * 131072 + r;
    O4[o]          = c;
    O4[o +  32768] = a;
    float4 p; p.x=c.x*a.x;  p.y=c.y*a.y;  p.z=c.z*a.z;  p.w=c.w*a.w;
    O4[o +  65536] = p;
    float4 g; g.x=c.x*bm.x; g.y=c.y*bm.y; g.z=c.z*bm.z; g.w=c.w*bm.w;
    O4[o +  98304] = g;
}

// ---------------- launch ----------------------------------------------------
extern "C" void kernel_launch(void* const* d_in, const int* in_sizes, int n_in,
                              void* d_out, int out_size)
{
    const float* C = (const float*)d_in[0];   // (B, D, CL)
    const float* Q = (const float*)d_in[1];   // (B, D, QL)
    const float* W = (const float*)d_in[2];   // (B*CL, 1, 3D)
    float* out = (float*)d_out;               // (B, 4D, CL)

    float *pAeff, *pbias, *pE2, *pLp, *pRp, *pinvl, *prinv, *pT, *pAt, *pBmt;
    cudaGetSymbolAddress((void**)&pAeff, g_Aeff);
    cudaGetSymbolAddress((void**)&pbias, g_bias);
    cudaGetSymbolAddress((void**)&pE2,   g_E2);
    cudaGetSymbolAddress((void**)&pLp,   g_Lp);
    cudaGetSymbolAddress((void**)&pRp,   g_Rp);
    cudaGetSymbolAddress((void**)&pinvl, g_invl);
    cudaGetSymbolAddress((void**)&prinv, g_rinv);
    cudaGetSymbolAddress((void**)&pT,    g_T);
    cudaGetSymbolAddress((void**)&pAt,   g_At);
    cudaGetSymbolAddress((void**)&pBmt,  g_Bmt);

    // K0: Aeff + bias
    prep_kernel<<<dim3(NCL / 32, NB), 256>>>(C, W, pAeff, pbias);

    // K1: E2 = exp(Aeff @ Q + bias[c]); column+row partial sums
    mma_gemm<false, 1, 128><<<dim3(NQL / 128, NCL / 128, NB), 256>>>(
        pAeff, Q, pE2, NCL, NQL, ND,
        (size_t)NCL * ND, (size_t)ND * NQL, (size_t)NCL * NQL,
        pbias, pLp, pRp);

    // combine -> invl[b][q], rinv[b][c]
    combine_k<<<NB * (NQL + NCL) / 256, 256>>>(pLp, pRp, pinvl, prinv);

    // K3: A^T[d][c] = rinv[c] * (Q @ E2^T)   (M=D, N=CL, K=QL)
    mma_gemm<true, 2, 128><<<dim3(NCL / 128, 1, NB), 256>>>(
        Q, pE2, pAt, ND, NCL, NQL,
        (size_t)ND * NQL, (size_t)NCL * NQL, (size_t)ND * NCL,
        prinv, nullptr, nullptr);

    // K4: T[d][q] = invl[q] * (C @ E2)       (M=D, N=QL, K=CL)  BN=64 -> 256 blocks
    mma_gemm<false, 2, 64><<<dim3(NQL / 64, 1, NB), 256>>>(
        C, pE2, pT, ND, NQL, NCL,
        (size_t)ND * NCL, (size_t)NCL * NQL, (size_t)ND * NQL,
        pinvl, nullptr, nullptr);

    // K5: Bm^T[d][c] = rinv[c] * (T @ E2^T)  (M=D, N=CL, K=QL)
    mma_gemm<true, 2, 128><<<dim3(NCL / 128, 1, NB), 256>>>(
        pT, pE2, pBmt, ND, NCL, NQL,
        (size_t)ND * NQL, (size_t)NCL * NQL, (size_t)ND * NCL,
        prinv, nullptr, nullptr);

    // K6: out = [C ; A^T ; C*A^T ; C*Bm^T]
    assemble_kernel<<<NB * ND * NCL / 4 / 256, 256>>>(C, pAt, pBmt, out);
}

// round 8
// speedup vs baseline: 2.9651x; 1.1253x over previous
#include <cuda_runtime.h>
#include <cstdint>

#define NB  32
#define ND  128
#define NCL 1024
#define NQL 512

// ---------------- scratch (device globals: allocation-free) ----------------
__device__ float g_Aeff[(size_t)NB * NCL * ND];     // Aeff[b][c][d]
__device__ float g_bias[(size_t)NB * NCL];          // bias[b][c]
__device__ float g_E2 [(size_t)NB * NCL * NQL];     // exp(S+bias)  [b][c][q]
__device__ float g_Lp [(size_t)NB * 8 * NQL];       // column partial sums
__device__ float g_Rp [(size_t)NB * 4 * NCL];       // row partial sums
__device__ float g_invl[(size_t)NB * NQL];          // 1 / column sum
__device__ float g_rinv[(size_t)NB * NCL];          // 1 / row sum
__device__ float g_T  [(size_t)NB * ND * NQL];      // T[b][d][q] = S2tC^T
__device__ float g_At [(size_t)NB * ND * NCL];      // A^T[b][d][c]
__device__ float g_Bmt[(size_t)NB * ND * NCL];      // Bm^T[b][d][c]

// ---------------- helpers ---------------------------------------------------
__device__ __forceinline__ uint32_t f2tf(float x) {
    uint32_t r; asm("cvt.rna.tf32.f32 %0, %1;" : "=r"(r) : "f"(x)); return r;
}
__device__ __forceinline__ void mma8(float* d, const uint32_t* a, const uint32_t* b) {
    asm("mma.sync.aligned.m16n8k8.row.col.f32.tf32.tf32.f32 "
        "{%0,%1,%2,%3}, {%4,%5,%6,%7}, {%8,%9}, {%0,%1,%2,%3};"
        : "+f"(d[0]), "+f"(d[1]), "+f"(d[2]), "+f"(d[3])
        : "r"(a[0]), "r"(a[1]), "r"(a[2]), "r"(a[3]), "r"(b[0]), "r"(b[1]));
}

// ---------------- K0: Aeff = wq + wqc*Ct ; bias = wc . Ct -------------------
__global__ __launch_bounds__(256) void prep_kernel(
    const float* __restrict__ C, const float* __restrict__ W,
    float* __restrict__ Aeff, float* __restrict__ bias)
{
    __shared__ float Csm[ND][33];
    const int b  = blockIdx.y;
    const int c0 = blockIdx.x * 32;
    const int t  = threadIdx.x;
    const float* Cb = C + (size_t)b * ND * NCL;

    #pragma unroll
    for (int i = 0; i < 16; i++) {
        int idx = i * 256 + t;
        int d = idx >> 5, c = idx & 31;
        Csm[d][c] = Cb[(size_t)d * NCL + c0 + c];
    }
    __syncthreads();

    #pragma unroll
    for (int i = 0; i < 16; i++) {
        int idx = i * 256 + t;
        int c = idx >> 7, d = idx & 127;
        size_t wb = (size_t)(b * NCL + c0 + c) * 384;
        float wq  = W[wb + d];
        float wqc = W[wb + 256 + d];
        Aeff[(size_t)(b * NCL + c0 + c) * ND + d] = wq + wqc * Csm[d][c];
    }

    int w = t >> 5, lane = t & 31;
    #pragma unroll
    for (int j = 0; j < 4; j++) {
        int c = w + j * 8;
        size_t wb = (size_t)(b * NCL + c0 + c) * 384 + 128;
        float s = 0.f;
        #pragma unroll
        for (int jj = 0; jj < 4; jj++) {
            int d = lane + jj * 32;
            s += W[wb + d] * Csm[d][c];
        }
        #pragma unroll
        for (int off = 16; off; off >>= 1)
            s += __shfl_xor_sync(0xffffffffu, s, off);
        if (lane == 0) bias[b * NCL + c0 + c] = s;
    }
}

// ---------------- tensor-core tf32 batched GEMM ------------------------------
// Double-buffered smem, fragment-native layouts, conflict-free B stores.
// MERGE: blockIdx.y selects (Aall -> Call) vs (Aall2 -> Call2), m0 = 0.
template <bool TRANSB, int EPI, int BN, bool MERGE>
__global__ __launch_bounds__(256, 2) void mma_gemm(
    const float* __restrict__ Aall, const float* __restrict__ Aall2,
    const float* __restrict__ Ball,
    float* __restrict__ Call, float* __restrict__ Call2,
    int M, int N, int K,
    size_t aStride, size_t bStride, size_t cStride,
    const float* __restrict__ xtra1,
    float* __restrict__ colpart, float* __restrict__ rowpart)
{
    constexpr int BM = 128, BK = 16;
    constexpr int NB8 = BN / 8;       // n-atoms per block (ks folded inside layout)
    constexpr int NI  = BN / 32;      // n-atoms per warp
    constexpr int BLD = BN / 64;      // B float4 loads per thread
    constexpr int BSZ = NB8 * 130 + 2;

    __shared__ uint32_t Asf[2][2 * 8 * 128];
    __shared__ uint32_t Bsf[2][BSZ];
    __shared__ float red_c[EPI == 1 ? 2 : 1][EPI == 1 ? BN : 1];
    __shared__ float red_r[EPI == 1 ? 4 : 1][EPI == 1 ? BM : 1];

    const int b  = blockIdx.z;
    const int n0 = blockIdx.x * BN;
    const int m0 = MERGE ? 0 : blockIdx.y * BM;
    const float* Abase = MERGE ? (blockIdx.y ? Aall2 : Aall) : Aall;
    float*       Cbase = MERGE ? (blockIdx.y ? Call2 : Call) : Call;
    const float* A  = Abase + (size_t)b * aStride + (size_t)m0 * K;
    const float* Bp = Ball + (size_t)b * bStride;
    float*       Cm = Cbase + (size_t)b * cStride;

    const int tid  = threadIdx.x;
    const int w    = tid >> 5;
    const int lane = tid & 31;
    const int g    = lane >> 2;
    const int t    = lane & 3;
    const int ma0  = (w >> 2) * 4;          // m-atom base for this warp
    const int na0  = (w & 3) * NI;          // n-atom base
    const int wm   = (w >> 2) * 64;
    const int wn   = (w & 3) * (8 * NI);
    const int swa  = lane ^ ((lane >> 3) & 3);   // A-frag load slot

    // ---- A loader precompute (2 float4 per thread) ----
    const float* pA[2];
    int aBase[2], aSwz[2];
    #pragma unroll
    for (int i = 0; i < 2; i++) {
        int lid = tid + i * 256;
        int r = lid >> 2, kq = lid & 3;
        pA[i] = A + (size_t)r * K + kq * 4;
        int im = r >> 4, gg = r & 7, h = (r >> 3) & 1;
        int ks = kq >> 1, reg = h + 2 * (kq & 1);
        aBase[i] = (ks * 8 + im) * 128 + gg * 16 + reg;
        aSwz[i]  = (gg >> 1) & 3;
    }
    // ---- B loader precompute ----
    // layout word(ks,in,g,t,kb) = in*130 + t*32 + ((g + 8*ks + 4*t)&15)*2 + kb
    const float* pB[BLD];
    int bBase[BLD], bG[BLD];
    if (TRANSB) {
        #pragma unroll
        for (int i = 0; i < BLD; i++) {
            int lid = tid + i * 256;
            int r = lid >> 2, kq = lid & 3;           // n-row r, k-quad kq (t = j)
            pB[i] = Bp + (size_t)(n0 + r) * K + kq * 4;
            int in = r >> 3, gg = r & 7, ks = kq >> 1, kb = kq & 1;
            bBase[i] = in * 130 + kb;                  // + j*32 + F*2 at store
            bG[i]    = gg + 8 * ks;
        }
    } else {
        #pragma unroll
        for (int i = 0; i < BLD; i++) {
            int lid = tid + i * 256;
            int r, q;
            if (BN == 128) { r = lid >> 5; q = lid & 31; }
            else           { r = lid >> 4; q = lid & 15; }
            pB[i] = Bp + (size_t)r * N + n0 + q * 4;
            int ks = r >> 3, tt = r & 3, kb = (r & 7) >> 2;
            int in = q >> 1, gb = 4 * (q & 1);
            bBase[i] = in * 130 + tt * 32 + kb;
            bG[i]    = gb + 8 * ks + 4 * tt;
        }
    }

    float acc[4][NI][4];
    #pragma unroll
    for (int i = 0; i < 4; i++)
        #pragma unroll
        for (int j = 0; j < NI; j++)
            #pragma unroll
            for (int r = 0; r < 4; r++) acc[i][j][r] = 0.f;

    // ---- prologue: load tile 0, store into buffer 0 ----
    float4 aR[2], bR[BLD];
    #pragma unroll
    for (int i = 0; i < 2; i++) aR[i] = *(const float4*)pA[i];
    #pragma unroll
    for (int i = 0; i < BLD; i++) bR[i] = *(const float4*)pB[i];

    #pragma unroll
    for (int i = 0; i < 2; i++) {
        float v[4] = {aR[i].x, aR[i].y, aR[i].z, aR[i].w};
        #pragma unroll
        for (int j = 0; j < 4; j++)
            Asf[0][aBase[i] + ((j ^ aSwz[i]) << 2)] = f2tf(v[j]);
    }
    #pragma unroll
    for (int i = 0; i < BLD; i++) {
        float v[4] = {bR[i].x, bR[i].y, bR[i].z, bR[i].w};
        if (TRANSB) {
            #pragma unroll
            for (int j = 0; j < 4; j++)
                Bsf[0][bBase[i] + j * 32 + (((bG[i] + 4 * j) & 15) << 1)] = f2tf(v[j]);
        } else {
            #pragma unroll
            for (int j = 0; j < 4; j++)
                Bsf[0][bBase[i] + (((bG[i] + j) & 15) << 1)] = f2tf(v[j]);
        }
    }
    __syncthreads();

    int buf = 0;
    for (int k0 = 0; k0 < K; k0 += BK) {
        const bool more = (k0 + BK < K);
        if (more) {
            #pragma unroll
            for (int i = 0; i < 2; i++) { pA[i] += BK; aR[i] = *(const float4*)pA[i]; }
            #pragma unroll
            for (int i = 0; i < BLD; i++) {
                pB[i] += TRANSB ? BK : (size_t)BK * N;
                bR[i] = *(const float4*)pB[i];
            }
        }

        #pragma unroll
        for (int ks = 0; ks < 2; ks++) {
            uint4 af[4];
            uint2 bf[NI];
            const uint32_t* ab = &Asf[buf][(ks * 8 + ma0) * 128 + swa * 4];
            #pragma unroll
            for (int im = 0; im < 4; im++)
                af[im] = *(const uint4*)(ab + im * 128);
            const uint32_t* bb = &Bsf[buf][t * 32 + (((g + 8 * ks + 4 * t) & 15) << 1)];
            #pragma unroll
            for (int in = 0; in < NI; in++)
                bf[in] = *(const uint2*)(bb + (na0 + in) * 130);
            #pragma unroll
            for (int im = 0; im < 4; im++)
                #pragma unroll
                for (int in = 0; in < NI; in++)
                    mma8(acc[im][in], (const uint32_t*)&af[im], (const uint32_t*)&bf[in]);
        }

        if (more) {
            int nb = buf ^ 1;
            #pragma unroll
            for (int i = 0; i < 2; i++) {
                float v[4] = {aR[i].x, aR[i].y, aR[i].z, aR[i].w};
                #pragma unroll
                for (int j = 0; j < 4; j++)
                    Asf[nb][aBase[i] + ((j ^ aSwz[i]) << 2)] = f2tf(v[j]);
            }
            #pragma unroll
            for (int i = 0; i < BLD; i++) {
                float v[4] = {bR[i].x, bR[i].y, bR[i].z, bR[i].w};
                if (TRANSB) {
                    #pragma unroll
                    for (int j = 0; j < 4; j++)
                        Bsf[nb][bBase[i] + j * 32 + (((bG[i] + 4 * j) & 15) << 1)] = f2tf(v[j]);
                } else {
                    #pragma unroll
                    for (int j = 0; j < 4; j++)
                        Bsf[nb][bBase[i] + (((bG[i] + j) & 15) << 1)] = f2tf(v[j]);
                }
            }
        }
        buf ^= 1;
        __syncthreads();
    }

    // ---------------- epilogue ----------------
    if constexpr (EPI == 1) {
        float bias_r[4][2];
        #pragma unroll
        for (int im = 0; im < 4; im++)
            #pragma unroll
            for (int h = 0; h < 2; h++)
                bias_r[im][h] = xtra1[(size_t)b * M + m0 + wm + im * 16 + g + 8 * h];

        float qs[NI][2];
        float rs[4][2];
        #pragma unroll
        for (int i = 0; i < NI; i++) { qs[i][0] = 0.f; qs[i][1] = 0.f; }
        #pragma unroll
        for (int i = 0; i < 4; i++)  { rs[i][0] = 0.f; rs[i][1] = 0.f; }

        #pragma unroll
        for (int im = 0; im < 4; im++)
            #pragma unroll
            for (int h = 0; h < 2; h++) {
                int m = m0 + wm + im * 16 + g + 8 * h;
                #pragma unroll
                for (int in = 0; in < NI; in++) {
                    float e0 = __expf(acc[im][in][2 * h]     + bias_r[im][h]);
                    float e1 = __expf(acc[im][in][2 * h + 1] + bias_r[im][h]);
                    float2 v; v.x = e0; v.y = e1;
                    *(float2*)&Cm[(size_t)m * N + n0 + wn + in * 8 + 2 * t] = v;
                    qs[in][0] += e0; qs[in][1] += e1;
                    rs[im][h] += e0 + e1;
                }
            }
        #pragma unroll
        for (int in = 0; in < NI; in++)
            #pragma unroll
            for (int j = 0; j < 2; j++) {
                float s = qs[in][j];
                s += __shfl_xor_sync(0xffffffffu, s, 16);
                s += __shfl_xor_sync(0xffffffffu, s, 8);
                s += __shfl_xor_sync(0xffffffffu, s, 4);
                if (g == 0) red_c[w >> 2][wn + in * 8 + 2 * t + j] = s;
            }
        #pragma unroll
        for (int im = 0; im < 4; im++)
            #pragma unroll
            for (int h = 0; h < 2; h++) {
                float s = rs[im][h];
                s += __shfl_xor_sync(0xffffffffu, s, 1);
                s += __shfl_xor_sync(0xffffffffu, s, 2);
                if (t == 0) red_r[w & 3][wm + im * 16 + g + 8 * h] = s;
            }
        __syncthreads();
        if (tid < BN) {
            colpart[((size_t)b * gridDim.y + blockIdx.y) * N + n0 + tid] =
                red_c[0][tid] + red_c[1][tid];
        } else if (tid < BN + BM) {
            int m = tid - BN;
            rowpart[((size_t)b * gridDim.x + blockIdx.x) * M + m0 + m] =
                red_r[0][m] + red_r[1][m] + red_r[2][m] + red_r[3][m];
        }
    } else {
        float sc[NI][2];
        if constexpr (EPI == 2) {
            #pragma unroll
            for (int in = 0; in < NI; in++)
                #pragma unroll
                for (int j = 0; j < 2; j++)
                    sc[in][j] = xtra1[(size_t)b * N + n0 + wn + in * 8 + 2 * t + j];
        }
        #pragma unroll
        for (int im = 0; im < 4; im++)
            #pragma unroll
            for (int h = 0; h < 2; h++) {
                int m = m0 + wm + im * 16 + g + 8 * h;
                #pragma unroll
                for (int in = 0; in < NI; in++) {
                    float2 v;
                    v.x = acc[im][in][2 * h];
                    v.y = acc[im][in][2 * h + 1];
                    if constexpr (EPI == 2) { v.x *= sc[in][0]; v.y *= sc[in][1]; }
                    *(float2*)&Cm[(size_t)m * N + n0 + wn + in * 8 + 2 * t] = v;
                }
            }
    }
}

// ---------------- combine partial sums -> invl (per q), rinv (per c) --------
__global__ __launch_bounds__(256) void combine_k(
    const float* __restrict__ Lp, const float* __restrict__ Rp,
    float* __restrict__ invl, float* __restrict__ rinv)
{
    int i = blockIdx.x * 256 + threadIdx.x;
    const int nbq = NB * NQL;
    if (i < nbq) {
        int b = i >> 9, q = i & 511;
        float s = 0.f;
        #pragma unroll
        for (int y = 0; y < 8; y++) s += Lp[((size_t)b * 8 + y) * NQL + q];
        invl[i] = 1.f / s;
    } else {
        int j = i - nbq;
        int b = j >> 10, c = j & 1023;
        float s = 0.f;
        #pragma unroll
        for (int x = 0; x < 4; x++) s += Rp[((size_t)b * 4 + x) * NCL + c];
        rinv[j] = 1.f / s;
    }
}

// ---------------- output assembly -------------------------------------------
__global__ __launch_bounds__(256) void assemble_kernel(
    const float* __restrict__ C, const float* __restrict__ At,
    const float* __restrict__ Bmt, float* __restrict__ out)
{
    size_t i = (size_t)blockIdx.x * 256 + threadIdx.x;
    size_t b = i >> 15;
    size_t r = i & 32767;
    const float4* C4 = (const float4*)C;
    const float4* A4 = (const float4*)At;
    const float4* B4 = (const float4*)Bmt;
    float4* O4 = (float4*)out;

    float4 c  = C4[i];
    float4 a  = A4[i];
    float4 bm = B4[i];
    size_t o = b * 131072 + r;
    O4[o]          = c;
    O4[o +  32768] = a;
    float4 p; p.x=c.x*a.x;  p.y=c.y*a.y;  p.z=c.z*a.z;  p.w=c.w*a.w;
    O4[o +  65536] = p;
    float4 g; g.x=c.x*bm.x; g.y=c.y*bm.y; g.z=c.z*bm.z; g.w=c.w*bm.w;
    O4[o +  98304] = g;
}

// ---------------- launch ----------------------------------------------------
extern "C" void kernel_launch(void* const* d_in, const int* in_sizes, int n_in,
                              void* d_out, int out_size)
{
    const float* C = (const float*)d_in[0];   // (B, D, CL)
    const float* Q = (const float*)d_in[1];   // (B, D, QL)
    const float* W = (const float*)d_in[2];   // (B*CL, 1, 3D)
    float* out = (float*)d_out;               // (B, 4D, CL)

    float *pAeff, *pbias, *pE2, *pLp, *pRp, *pinvl, *prinv, *pT, *pAt, *pBmt;
    cudaGetSymbolAddress((void**)&pAeff, g_Aeff);
    cudaGetSymbolAddress((void**)&pbias, g_bias);
    cudaGetSymbolAddress((void**)&pE2,   g_E2);
    cudaGetSymbolAddress((void**)&pLp,   g_Lp);
    cudaGetSymbolAddress((void**)&pRp,   g_Rp);
    cudaGetSymbolAddress((void**)&pinvl, g_invl);
    cudaGetSymbolAddress((void**)&prinv, g_rinv);
    cudaGetSymbolAddress((void**)&pT,    g_T);
    cudaGetSymbolAddress((void**)&pAt,   g_At);
    cudaGetSymbolAddress((void**)&pBmt,  g_Bmt);

    // K0: Aeff + bias
    prep_kernel<<<dim3(NCL / 32, NB), 256>>>(C, W, pAeff, pbias);

    // K1: E2 = exp(Aeff @ Q + bias[c]); column+row partial sums
    mma_gemm<false, 1, 128, false><<<dim3(NQL / 128, NCL / 128, NB), 256>>>(
        pAeff, nullptr, Q, pE2, nullptr, NCL, NQL, ND,
        (size_t)NCL * ND, (size_t)ND * NQL, (size_t)NCL * NQL,
        pbias, pLp, pRp);

    // combine -> invl[b][q], rinv[b][c]
    combine_k<<<NB * (NQL + NCL) / 256, 256>>>(pLp, pRp, pinvl, prinv);

    // K4: T[d][q] = invl[q] * (C @ E2)       (M=D, N=QL, K=CL)
    mma_gemm<false, 2, 64, false><<<dim3(NQL / 64, 1, NB), 256>>>(
        C, nullptr, pE2, pT, nullptr, ND, NQL, NCL,
        (size_t)ND * NCL, (size_t)NCL * NQL, (size_t)ND * NQL,
        pinvl, nullptr, nullptr);

    // K3+K5 merged: y=0: A^T = rinv[c]*(Q @ E2^T); y=1: Bm^T = rinv[c]*(T @ E2^T)
    mma_gemm<true, 2, 128, true><<<dim3(NCL / 128, 2, NB), 256>>>(
        Q, pT, pE2, pAt, pBmt, ND, NCL, NQL,
        (size_t)ND * NQL, (size_t)NCL * NQL, (size_t)ND * NCL,
        prinv, nullptr, nullptr);

    // K6: out = [C ; A^T ; C*A^T ; C*Bm^T]
    assemble_kernel<<<NB * ND * NCL / 4 / 256, 256>>>(C, pAt, pBmt, out);
}

// round 10
// speedup vs baseline: 3.9028x; 1.3162x over previous
#include <cuda_runtime.h>
#include <cstdint>

#define NB  32
#define ND  128
#define NCL 1024
#define NQL 512

// ---------------- scratch (device globals: allocation-free) ----------------
__device__ float g_Aeff[(size_t)NB * NCL * ND];     // Aeff[b][c][d]
__device__ float g_bias[(size_t)NB * NCL];          // bias[b][c]
__device__ float g_E2 [(size_t)NB * NCL * NQL];     // exp(S+bias)  [b][c][q]
__device__ float g_Lp [(size_t)NB * 8 * NQL];       // column partial sums
__device__ float g_Rp [(size_t)NB * 4 * NCL];       // row partial sums
__device__ float g_invl[(size_t)NB * NQL];          // 1 / column sum
__device__ float g_rinv[(size_t)NB * NCL];          // 1 / row sum
__device__ float g_T  [(size_t)NB * ND * NQL];      // T[b][d][q] = S2tC^T
__device__ float g_At [(size_t)NB * ND * NCL];      // A^T[b][d][c]
__device__ float g_Bmt[(size_t)NB * ND * NCL];      // Bm^T[b][d][c]

// ---------------- helpers ---------------------------------------------------
__device__ __forceinline__ void mma8(float* d, const uint32_t* a, const uint32_t* b) {
    asm("mma.sync.aligned.m16n8k8.row.col.f32.tf32.tf32.f32 "
        "{%0,%1,%2,%3}, {%4,%5,%6,%7}, {%8,%9}, {%0,%1,%2,%3};"
        : "+f"(d[0]), "+f"(d[1]), "+f"(d[2]), "+f"(d[3])
        : "r"(a[0]), "r"(a[1]), "r"(a[2]), "r"(a[3]), "r"(b[0]), "r"(b[1]));
}
__device__ __forceinline__ uint4 ldsm4(uint32_t addr) {
    uint4 r;
    asm volatile("ldmatrix.sync.aligned.m8n8.x4.shared.b16 {%0,%1,%2,%3}, [%4];"
                 : "=r"(r.x), "=r"(r.y), "=r"(r.z), "=r"(r.w) : "r"(addr));
    return r;
}
#define CP16(dst, src) \
    asm volatile("cp.async.cg.shared.global [%0], [%1], 16;" :: "r"(dst), "l"(src))
#define CPCOMMIT() asm volatile("cp.async.commit_group;" ::)
#define CPWAIT1()  asm volatile("cp.async.wait_group 1;" ::: "memory")

// ---------------- K0: Aeff = wq + wqc*Ct ; bias = wc . Ct -------------------
__global__ __launch_bounds__(256) void prep_kernel(
    const float* __restrict__ C, const float* __restrict__ W,
    float* __restrict__ Aeff, float* __restrict__ bias)
{
    __shared__ float Csm[ND][33];
    const int b  = blockIdx.y;
    const int c0 = blockIdx.x * 32;
    const int t  = threadIdx.x;
    const float* Cb = C + (size_t)b * ND * NCL;

    #pragma unroll
    for (int i = 0; i < 16; i++) {
        int idx = i * 256 + t;
        int d = idx >> 5, c = idx & 31;
        Csm[d][c] = Cb[(size_t)d * NCL + c0 + c];
    }
    __syncthreads();

    #pragma unroll
    for (int i = 0; i < 16; i++) {
        int idx = i * 256 + t;
        int c = idx >> 7, d = idx & 127;
        size_t wb = (size_t)(b * NCL + c0 + c) * 384;
        float wq  = W[wb + d];
        float wqc = W[wb + 256 + d];
        Aeff[(size_t)(b * NCL + c0 + c) * ND + d] = wq + wqc * Csm[d][c];
    }

    int w = t >> 5, lane = t & 31;
    #pragma unroll
    for (int j = 0; j < 4; j++) {
        int c = w + j * 8;
        size_t wb = (size_t)(b * NCL + c0 + c) * 384 + 128;
        float s = 0.f;
        #pragma unroll
        for (int jj = 0; jj < 4; jj++) {
            int d = lane + jj * 32;
            s += W[wb + d] * Csm[d][c];
        }
        #pragma unroll
        for (int off = 16; off; off >>= 1)
            s += __shfl_xor_sync(0xffffffffu, s, off);
        if (lane == 0) bias[b * NCL + c0 + c] = s;
    }
}

// ---------------- tf32 tensor-core GEMM: cp.async + ldmatrix pipeline --------
// Cout[M x N] = A[M x K rm] @ B (B: K x N rm if !TRANSB, else N x K rm).
// 3-stage cp.async ring; smem tiles row-major with XOR swizzle; ldmatrix frags.
template <bool TRANSB, int EPI, int BN, bool MERGE>
__global__ __launch_bounds__(256, 2) void mma_gemm(
    const float* __restrict__ Aall, const float* __restrict__ Aall2,
    const float* __restrict__ Ball,
    float* __restrict__ Call, float* __restrict__ Call2,
    int M, int N, int K,
    size_t aStride, size_t bStride, size_t cStride,
    const float* __restrict__ xtra1,
    float* __restrict__ colpart, float* __restrict__ rowpart)
{
    constexpr int BM = 128, BK = 16, STG = 3;
    constexpr int NI = BN / 32;
    constexpr int ABYTES = BM * BK * 4;   // 8192
    constexpr int BBYTES = BK * BN * 4;   // 8192 / 4096

    __shared__ float As[STG][BM * BK];
    __shared__ float Bs[STG][BK * BN];

    const int b  = blockIdx.z;
    const int n0 = blockIdx.x * BN;
    const int m0 = MERGE ? 0 : blockIdx.y * BM;
    const float* Abase = MERGE ? (blockIdx.y ? Aall2 : Aall) : Aall;
    float*       Cbase = MERGE ? (blockIdx.y ? Call2 : Call) : Call;
    const float* A  = Abase + (size_t)b * aStride + (size_t)m0 * K;
    const float* Bp = Ball + (size_t)b * bStride;
    float*       Cm = Cbase + (size_t)b * cStride;

    const int tid  = threadIdx.x;
    const int w    = tid >> 5;
    const int lane = tid & 31;
    const int g    = lane >> 2;
    const int t    = lane & 3;
    const int na0  = (w & 3) * NI;
    const int wm   = (w >> 2) * 64;
    const int wn   = (w & 3) * (8 * NI);

    const uint32_t sAu = (uint32_t)__cvta_generic_to_shared(&As[0][0]);
    const uint32_t sBu = (uint32_t)__cvta_generic_to_shared(&Bs[0][0]);
    const int T = K / BK;

    // ---- global->smem loader setup (16B chunks, swizzled dst) ----
    // A: 128 rows x 16k: thread -> rows r, r+64; chunk c = tid&3
    const int rA = tid >> 2, cA = tid & 3;
    const float* gA0 = A + (size_t)rA * K + cA * 4;
    const float* gA1 = gA0 + (size_t)64 * K;
    const uint32_t dA0 = sAu + ((rA * 4 + (cA ^ ((rA >> 1) & 3))) << 4);
    const uint32_t dA1 = dA0 + 4096;

    const float* gB0;
    const float* gB1 = nullptr;
    uint32_t dB0, dB1 = 0;
    if (TRANSB) {
        const int rB = tid >> 2, cB = tid & 3;
        gB0 = Bp + (size_t)(n0 + rB) * K + cB * 4;
        dB0 = sBu + ((rB * 4 + (cB ^ ((rB >> 1) & 3))) << 4);
        if (BN == 128) { gB1 = gB0 + (size_t)64 * K; dB1 = dB0 + 4096; }
    } else {
        const int kB = tid >> 4, cB = tid & 15;
        gB0 = Bp + (size_t)kB * N + n0 + cB * 4;
        dB0 = sBu + ((kB * (BN / 4) + (cB ^ (2 * (kB & 3)))) << 4);
        if (BN == 128) { gB1 = gB0 + 64; dB1 = dB0 + 256; }
    }

    auto issue_tile = [&](int stage) {
        const uint32_t ao = stage * ABYTES, bo = stage * BBYTES;
        CP16(dA0 + ao, gA0); CP16(dA1 + ao, gA1);
        gA0 += BK; gA1 += BK;
        CP16(dB0 + bo, gB0);
        if (BN == 128) CP16(dB1 + bo, gB1);
        if (TRANSB) { gB0 += BK; if (BN == 128) gB1 += BK; }
        else        { gB0 += (size_t)BK * N; if (BN == 128) gB1 += (size_t)BK * N; }
    };

    // ---- fragment address precompute ----
    // A frag (ldmatrix.x4): mats (m-lo/k-lo, m-hi/k-lo, m-lo/k-hi, m-hi/k-hi)
    const int aRow = wm + ((lane >> 3) & 1) * 8 + (lane & 7);
    const int aSel = lane >> 4;
    const int fSwz = (lane >> 1) & 3;
    const int aB0  = aRow * 64;
    const int ax[2] = { ((aSel) ^ fSwz) << 4, ((2 + aSel) ^ fSwz) << 4 };

    // B TRANS frag (ldmatrix.x4 per atom-pair)
    int bRB[TRANSB ? (NI / 2) : 1];
    int bx0 = 0, bx1 = 0;
    if (TRANSB) {
        const int bSel = (lane >> 3) & 1;
        bx0 = ((bSel) ^ fSwz) << 4;
        bx1 = ((2 + bSel) ^ fSwz) << 4;
        #pragma unroll
        for (int p = 0; p < NI / 2; p++)
            bRB[p] = ((na0 + 2 * p + (lane >> 4)) * 8 + (lane & 7)) * 64;
    }
    // B non-TRANS frag (LDS.32): word col within row (swizzled), row offsets
    int colB[TRANSB ? 1 : NI];
    int rw0 = 0, rw1 = 0;
    if (!TRANSB) {
        #pragma unroll
        for (int in = 0; in < NI; in++) {
            int cn = (wn >> 2) + in * 2 + (g >> 2);
            colB[in] = ((cn ^ (2 * t)) << 2) + (g & 3);
        }
        rw0 = t * BN;            // ks=0 rows t / t+4
        rw1 = (8 + t) * BN;      // ks=1
    }

    float acc[4][NI][4];
    #pragma unroll
    for (int i = 0; i < 4; i++)
        #pragma unroll
        for (int j = 0; j < NI; j++)
            #pragma unroll
            for (int r = 0; r < 4; r++) acc[i][j][r] = 0.f;

    // ---- prologue: 2 stages in flight ----
    issue_tile(0); CPCOMMIT();
    issue_tile(1); CPCOMMIT();

    for (int it = 0; it < T; ++it) {
        CPWAIT1();
        __syncthreads();
        if (it + 2 < T) issue_tile((it + 2) % STG);
        CPCOMMIT();

        const int st = it % STG;
        const uint32_t aSt = sAu + st * ABYTES;
        const uint32_t bSt = sBu + st * BBYTES;
        const uint32_t* Bw = (const uint32_t*)&Bs[st][0];

        #pragma unroll
        for (int ks = 0; ks < 2; ks++) {
            uint4 af[4];
            #pragma unroll
            for (int im = 0; im < 4; im++)
                af[im] = ldsm4(aSt + aB0 + im * 1024 + ax[ks]);

            uint32_t bf[NI][2];
            if (TRANSB) {
                #pragma unroll
                for (int p = 0; p < NI / 2; p++) {
                    uint4 bv = ldsm4(bSt + bRB[p] + (ks ? bx1 : bx0));
                    bf[2 * p][0] = bv.x; bf[2 * p][1] = bv.y;
                    bf[2 * p + 1][0] = bv.z; bf[2 * p + 1][1] = bv.w;
                }
            } else {
                const int rw = ks ? rw1 : rw0;
                #pragma unroll
                for (int in = 0; in < NI; in++) {
                    bf[in][0] = Bw[rw + colB[in]];
                    bf[in][1] = Bw[rw + colB[in] + 4 * BN];
                }
            }
            #pragma unroll
            for (int im = 0; im < 4; im++)
                #pragma unroll
                for (int in = 0; in < NI; in++)
                    mma8(acc[im][in], (const uint32_t*)&af[im], bf[in]);
        }
    }

    // ---------------- epilogue ----------------
    if constexpr (EPI == 1) {
        float bias_r[4][2];
        #pragma unroll
        for (int im = 0; im < 4; im++)
            #pragma unroll
            for (int h = 0; h < 2; h++)
                bias_r[im][h] = xtra1[(size_t)b * M + m0 + wm + im * 16 + g + 8 * h];

        float qs[NI][2];
        float rs[4][2];
        #pragma unroll
        for (int i = 0; i < NI; i++) { qs[i][0] = 0.f; qs[i][1] = 0.f; }
        #pragma unroll
        for (int i = 0; i < 4; i++)  { rs[i][0] = 0.f; rs[i][1] = 0.f; }

        #pragma unroll
        for (int im = 0; im < 4; im++)
            #pragma unroll
            for (int h = 0; h < 2; h++) {
                int m = m0 + wm + im * 16 + g + 8 * h;
                #pragma unroll
                for (int in = 0; in < NI; in++) {
                    float e0 = __expf(acc[im][in][2 * h]     + bias_r[im][h]);
                    float e1 = __expf(acc[im][in][2 * h + 1] + bias_r[im][h]);
                    float2 v; v.x = e0; v.y = e1;
                    *(float2*)&Cm[(size_t)m * N + n0 + wn + in * 8 + 2 * t] = v;
                    qs[in][0] += e0; qs[in][1] += e1;
                    rs[im][h] += e0 + e1;
                }
            }
        // reductions staged through smem aliased onto As (mainloop done)
        __syncthreads();
        float* red_c = (float*)&As[0][0];            // [2][BN]
        float* red_r = ((float*)&As[0][0]) + 2 * BN; // [4][BM]
        #pragma unroll
        for (int in = 0; in < NI; in++)
            #pragma unroll
            for (int j = 0; j < 2; j++) {
                float s = qs[in][j];
                s += __shfl_xor_sync(0xffffffffu, s, 16);
                s += __shfl_xor_sync(0xffffffffu, s, 8);
                s += __shfl_xor_sync(0xffffffffu, s, 4);
                if (g == 0) red_c[(w >> 2) * BN + wn + in * 8 + 2 * t + j] = s;
            }
        #pragma unroll
        for (int im = 0; im < 4; im++)
            #pragma unroll
            for (int h = 0; h < 2; h++) {
                float s = rs[im][h];
                s += __shfl_xor_sync(0xffffffffu, s, 1);
                s += __shfl_xor_sync(0xffffffffu, s, 2);
                if (t == 0) red_r[(w & 3) * BM + wm + im * 16 + g + 8 * h] = s;
            }
        __syncthreads();
        if (tid < BN) {
            colpart[((size_t)b * gridDim.y + blockIdx.y) * N + n0 + tid] =
                red_c[tid] + red_c[BN + tid];
        } else if (tid < BN + BM) {
            int m = tid - BN;
            rowpart[((size_t)b * gridDim.x + blockIdx.x) * M + m0 + m] =
                red_r[m] + red_r[BM + m] + red_r[2 * BM + m] + red_r[3 * BM + m];
        }
    } else {
        float sc[NI][2];
        if constexpr (EPI == 2) {
            #pragma unroll
            for (int in = 0; in < NI; in++)
                #pragma unroll
                for (int j = 0; j < 2; j++)
                    sc[in][j] = xtra1[(size_t)b * N + n0 + wn + in * 8 + 2 * t + j];
        }
        #pragma unroll
        for (int im = 0; im < 4; im++)
            #pragma unroll
            for (int h = 0; h < 2; h++) {
                int m = m0 + wm + im * 16 + g + 8 * h;
                #pragma unroll
                for (int in = 0; in < NI; in++) {
                    float2 v;
                    v.x = acc[im][in][2 * h];
                    v.y = acc[im][in][2 * h + 1];
                    if constexpr (EPI == 2) { v.x *= sc[in][0]; v.y *= sc[in][1]; }
                    *(float2*)&Cm[(size_t)m * N + n0 + wn + in * 8 + 2 * t] = v;
                }
            }
    }
}

// ---------------- combine partial sums -> invl (per q), rinv (per c) --------
__global__ __launch_bounds__(256) void combine_k(
    const float* __restrict__ Lp, const float* __restrict__ Rp,
    float* __restrict__ invl, float* __restrict__ rinv)
{
    int i = blockIdx.x * 256 + threadIdx.x;
    const int nbq = NB * NQL;
    if (i < nbq) {
        int b = i >> 9, q = i & 511;
        float s = 0.f;
        #pragma unroll
        for (int y = 0; y < 8; y++) s += Lp[((size_t)b * 8 + y) * NQL + q];
        invl[i] = 1.f / s;
    } else {
        int j = i - nbq;
        int b = j >> 10, c = j & 1023;
        float s = 0.f;
        #pragma unroll
        for (int x = 0; x < 4; x++) s += Rp[((size_t)b * 4 + x) * NCL + c];
        rinv[j] = 1.f / s;
    }
}

// ---------------- output assembly -------------------------------------------
__global__ __launch_bounds__(256) void assemble_kernel(
    const float* __restrict__ C, const float* __restrict__ At,
    const float* __restrict__ Bmt, float* __restrict__ out)
{
    size_t i = (size_t)blockIdx.x * 256 + threadIdx.x;
    size_t b = i >> 15;
    size_t r = i & 32767;
    const float4* C4 = (const float4*)C;
    const float4* A4 = (const float4*)At;
    const float4* B4 = (const float4*)Bmt;
    float4* O4 = (float4*)out;

    float4 c  = C4[i];
    float4 a  = A4[i];
    float4 bm = B4[i];
    size_t o = b * 131072 + r;
    O4[o]          = c;
    O4[o +  32768] = a;
    float4 p; p.x=c.x*a.x;  p.y=c.y*a.y;  p.z=c.z*a.z;  p.w=c.w*a.w;
    O4[o +  65536] = p;
    float4 g; g.x=c.x*bm.x; g.y=c.y*bm.y; g.z=c.z*bm.z; g.w=c.w*bm.w;
    O4[o +  98304] = g;
}

// ---------------- launch ----------------------------------------------------
extern "C" void kernel_launch(void* const* d_in, const int* in_sizes, int n_in,
                              void* d_out, int out_size)
{
    const float* C = (const float*)d_in[0];   // (B, D, CL)
    const float* Q = (const float*)d_in[1];   // (B, D, QL)
    const float* W = (const float*)d_in[2];   // (B*CL, 1, 3D)
    float* out = (float*)d_out;               // (B, 4D, CL)

    float *pAeff, *pbias, *pE2, *pLp, *pRp, *pinvl, *prinv, *pT, *pAt, *pBmt;
    cudaGetSymbolAddress((void**)&pAeff, g_Aeff);
    cudaGetSymbolAddress((void**)&pbias, g_bias);
    cudaGetSymbolAddress((void**)&pE2,   g_E2);
    cudaGetSymbolAddress((void**)&pLp,   g_Lp);
    cudaGetSymbolAddress((void**)&pRp,   g_Rp);
    cudaGetSymbolAddress((void**)&pinvl, g_invl);
    cudaGetSymbolAddress((void**)&prinv, g_rinv);
    cudaGetSymbolAddress((void**)&pT,    g_T);
    cudaGetSymbolAddress((void**)&pAt,   g_At);
    cudaGetSymbolAddress((void**)&pBmt,  g_Bmt);

    // K0: Aeff + bias
    prep_kernel<<<dim3(NCL / 32, NB), 256>>>(C, W, pAeff, pbias);

    // K1: E2 = exp(Aeff @ Q + bias[c]); column+row partial sums
    mma_gemm<false, 1, 128, false><<<dim3(NQL / 128, NCL / 128, NB), 256>>>(
        pAeff, nullptr, Q, pE2, nullptr, NCL, NQL, ND,
        (size_t)NCL * ND, (size_t)ND * NQL, (size_t)NCL * NQL,
        pbias, pLp, pRp);

    // combine -> invl[b][q], rinv[b][c]
    combine_k<<<NB * (NQL + NCL) / 256, 256>>>(pLp, pRp, pinvl, prinv);

    // K4: T[d][q] = invl[q] * (C @ E2)       (M=D, N=QL, K=CL)
    mma_gemm<false, 2, 64, false><<<dim3(NQL / 64, 1, NB), 256>>>(
        C, nullptr, pE2, pT, nullptr, ND, NQL, NCL,
        (size_t)ND * NCL, (size_t)NCL * NQL, (size_t)ND * NQL,
        pinvl, nullptr, nullptr);

    // K3+K5 merged: y=0: A^T = rinv[c]*(Q @ E2^T); y=1: Bm^T = rinv[c]*(T @ E2^T)
    mma_gemm<true, 2, 128, true><<<dim3(NCL / 128, 2, NB), 256>>>(
        Q, pT, pE2, pAt, pBmt, ND, NCL, NQL,
        (size_t)ND * NQL, (size_t)NCL * NQL, (size_t)ND * NCL,
        prinv, nullptr, nullptr);

    // K6: out = [C ; A^T ; C*A^T ; C*Bm^T]
    assemble_kernel<<<NB * ND * NCL / 4 / 256, 256>>>(C, pAt, pBmt, out);
}

// round 11
// speedup vs baseline: 4.2670x; 1.0933x over previous
#include <cuda_runtime.h>
#include <cstdint>

#define NB  32
#define ND  128
#define NCL 1024
#define NQL 512

// ---------------- scratch (device globals: allocation-free) ----------------
__device__ float g_Aeff[(size_t)NB * NCL * ND];     // Aeff[b][c][d]
__device__ float g_bias[(size_t)NB * NCL];          // bias[b][c]
__device__ float g_E2 [(size_t)NB * NCL * NQL];     // exp(S+bias)  [b][c][q]
__device__ float g_Lp [(size_t)NB * 8 * NQL];       // column partial sums
__device__ float g_Rp [(size_t)NB * 4 * NCL];       // row partial sums
__device__ float g_invl[(size_t)NB * NQL];          // 1 / column sum
__device__ float g_rinv[(size_t)NB * NCL];          // 1 / row sum
__device__ float g_T  [(size_t)NB * ND * NQL];      // T[b][d][q] = S2tC^T

// ---------------- helpers ---------------------------------------------------
__device__ __forceinline__ void mma8(float* d, const uint32_t* a, const uint32_t* b) {
    asm("mma.sync.aligned.m16n8k8.row.col.f32.tf32.tf32.f32 "
        "{%0,%1,%2,%3}, {%4,%5,%6,%7}, {%8,%9}, {%0,%1,%2,%3};"
        : "+f"(d[0]), "+f"(d[1]), "+f"(d[2]), "+f"(d[3])
        : "r"(a[0]), "r"(a[1]), "r"(a[2]), "r"(a[3]), "r"(b[0]), "r"(b[1]));
}
__device__ __forceinline__ uint4 ldsm4(uint32_t addr) {
    uint4 r;
    asm volatile("ldmatrix.sync.aligned.m8n8.x4.shared.b16 {%0,%1,%2,%3}, [%4];"
                 : "=r"(r.x), "=r"(r.y), "=r"(r.z), "=r"(r.w) : "r"(addr));
    return r;
}
#define CP16(dst, src) \
    asm volatile("cp.async.cg.shared.global [%0], [%1], 16;" :: "r"(dst), "l"(src))
#define CPCOMMIT() asm volatile("cp.async.commit_group;" ::)
#define CPWAIT2()  asm volatile("cp.async.wait_group 2;" ::: "memory")

// ---------------- K0: Aeff = wq + wqc*Ct ; bias = wc . Ct ; out[sec0]=C -----
__global__ __launch_bounds__(256) void prep_kernel(
    const float* __restrict__ C, const float* __restrict__ W,
    float* __restrict__ Aeff, float* __restrict__ bias,
    float* __restrict__ out)
{
    __shared__ float Csm[ND][33];
    const int b  = blockIdx.y;
    const int c0 = blockIdx.x * 32;
    const int t  = threadIdx.x;
    const float* Cb = C + (size_t)b * ND * NCL;
    float* Ob = out + (size_t)b * 4 * ND * NCL;

    #pragma unroll
    for (int i = 0; i < 16; i++) {
        int idx = i * 256 + t;
        int d = idx >> 5, c = idx & 31;
        float v = Cb[(size_t)d * NCL + c0 + c];
        Csm[d][c] = v;
        Ob[(size_t)d * NCL + c0 + c] = v;   // out section 0 = C
    }
    __syncthreads();

    #pragma unroll
    for (int i = 0; i < 16; i++) {
        int idx = i * 256 + t;
        int c = idx >> 7, d = idx & 127;
        size_t wb = (size_t)(b * NCL + c0 + c) * 384;
        float wq  = W[wb + d];
        float wqc = W[wb + 256 + d];
        Aeff[(size_t)(b * NCL + c0 + c) * ND + d] = wq + wqc * Csm[d][c];
    }

    int w = t >> 5, lane = t & 31;
    #pragma unroll
    for (int j = 0; j < 4; j++) {
        int c = w + j * 8;
        size_t wb = (size_t)(b * NCL + c0 + c) * 384 + 128;
        float s = 0.f;
        #pragma unroll
        for (int jj = 0; jj < 4; jj++) {
            int d = lane + jj * 32;
            s += W[wb + d] * Csm[d][c];
        }
        #pragma unroll
        for (int off = 16; off; off >>= 1)
            s += __shfl_xor_sync(0xffffffffu, s, off);
        if (lane == 0) bias[b * NCL + c0 + c] = s;
    }
}

// ---------------- tf32 tensor-core GEMM: cp.async + ldmatrix pipeline --------
// 4-stage cp.async ring (3 tiles in flight), dynamic smem, swizzled tiles.
// EPI=1: store exp(acc+bias[m]) + col/row partial sums (K1).
// EPI=2 & !MERGE: C = acc * xtra1[col]  (K4 -> T).
// EPI=2 & MERGE : fused final assembly: v = acc * rinv[col]; cv = C[m][col];
//   y=0 -> out[sec1]=v, out[sec2]=cv*v ; y=1 -> out[sec3]=cv*v.
template <bool TRANSB, int EPI, int BN, bool MERGE>
__global__ __launch_bounds__(256, 2) void mma_gemm(
    const float* __restrict__ Aall, const float* __restrict__ Aall2,
    const float* __restrict__ Ball,
    float* __restrict__ Call, const float* __restrict__ Cprod,
    int M, int N, int K,
    size_t aStride, size_t bStride, size_t cStride,
    const float* __restrict__ xtra1,
    float* __restrict__ colpart, float* __restrict__ rowpart)
{
    constexpr int BM = 128, BK = 16, STG = 4;
    constexpr int NI = BN / 32;
    constexpr int ABYTES = BM * BK * 4;   // 8192
    constexpr int BBYTES = BK * BN * 4;   // 8192 / 4096

    extern __shared__ float sdyn[];
    float* As = sdyn;                          // STG * BM*BK
    float* Bs = sdyn + STG * BM * BK;          // STG * BK*BN

    const int b  = blockIdx.z;
    const int n0 = blockIdx.x * BN;
    const int m0 = MERGE ? 0 : blockIdx.y * BM;
    const float* Abase = MERGE ? (blockIdx.y ? Aall2 : Aall) : Aall;
    const float* A  = Abase + (size_t)b * aStride + (size_t)m0 * K;
    const float* Bp = Ball + (size_t)b * bStride;
    float*       Cm = Call + (size_t)b * cStride;

    const int tid  = threadIdx.x;
    const int w    = tid >> 5;
    const int lane = tid & 31;
    const int g    = lane >> 2;
    const int t    = lane & 3;
    const int na0  = (w & 3) * NI;
    const int wm   = (w >> 2) * 64;
    const int wn   = (w & 3) * (8 * NI);

    const uint32_t sAu = (uint32_t)__cvta_generic_to_shared(As);
    const uint32_t sBu = (uint32_t)__cvta_generic_to_shared(Bs);
    const int T = K / BK;

    // ---- global->smem loader setup (16B chunks, swizzled dst) ----
    const int rA = tid >> 2, cA = tid & 3;
    const float* gA0 = A + (size_t)rA * K + cA * 4;
    const float* gA1 = gA0 + (size_t)64 * K;
    const uint32_t dA0 = sAu + ((rA * 4 + (cA ^ ((rA >> 1) & 3))) << 4);
    const uint32_t dA1 = dA0 + 4096;

    const float* gB0;
    const float* gB1 = nullptr;
    uint32_t dB0, dB1 = 0;
    if (TRANSB) {
        const int rB = tid >> 2, cB = tid & 3;
        gB0 = Bp + (size_t)(n0 + rB) * K + cB * 4;
        dB0 = sBu + ((rB * 4 + (cB ^ ((rB >> 1) & 3))) << 4);
        if (BN == 128) { gB1 = gB0 + (size_t)64 * K; dB1 = dB0 + 4096; }
    } else {
        const int kB = tid >> 4, cB = tid & 15;
        gB0 = Bp + (size_t)kB * N + n0 + cB * 4;
        dB0 = sBu + ((kB * (BN / 4) + (cB ^ (2 * (kB & 3)))) << 4);
        if (BN == 128) { gB1 = gB0 + 64; dB1 = dB0 + 256; }
    }

    auto issue_tile = [&](int stage) {
        const uint32_t ao = stage * ABYTES, bo = stage * BBYTES;
        CP16(dA0 + ao, gA0); CP16(dA1 + ao, gA1);
        gA0 += BK; gA1 += BK;
        CP16(dB0 + bo, gB0);
        if (BN == 128) CP16(dB1 + bo, gB1);
        if (TRANSB) { gB0 += BK; if (BN == 128) gB1 += BK; }
        else        { gB0 += (size_t)BK * N; if (BN == 128) gB1 += (size_t)BK * N; }
    };

    // ---- fragment address precompute ----
    const int aRow = wm + ((lane >> 3) & 1) * 8 + (lane & 7);
    const int aSel = lane >> 4;
    const int fSwz = (lane >> 1) & 3;
    const int aB0  = aRow * 64;
    const int ax[2] = { ((aSel) ^ fSwz) << 4, ((2 + aSel) ^ fSwz) << 4 };

    int bRB[TRANSB ? (NI / 2) : 1];
    int bx0 = 0, bx1 = 0;
    if (TRANSB) {
        const int bSel = (lane >> 3) & 1;
        bx0 = ((bSel) ^ fSwz) << 4;
        bx1 = ((2 + bSel) ^ fSwz) << 4;
        #pragma unroll
        for (int p = 0; p < NI / 2; p++)
            bRB[p] = ((na0 + 2 * p + (lane >> 4)) * 8 + (lane & 7)) * 64;
    }
    int colB[TRANSB ? 1 : NI];
    int rw0 = 0, rw1 = 0;
    if (!TRANSB) {
        #pragma unroll
        for (int in = 0; in < NI; in++) {
            int cn = (wn >> 2) + in * 2 + (g >> 2);
            colB[in] = ((cn ^ (2 * t)) << 2) + (g & 3);
        }
        rw0 = t * BN;
        rw1 = (8 + t) * BN;
    }

    float acc[4][NI][4];
    #pragma unroll
    for (int i = 0; i < 4; i++)
        #pragma unroll
        for (int j = 0; j < NI; j++)
            #pragma unroll
            for (int r = 0; r < 4; r++) acc[i][j][r] = 0.f;

    // ---- prologue: 3 stages in flight ----
    issue_tile(0); CPCOMMIT();
    issue_tile(1); CPCOMMIT();
    issue_tile(2); CPCOMMIT();

    for (int it = 0; it < T; ++it) {
        CPWAIT2();
        __syncthreads();
        if (it + 3 < T) issue_tile((it + 3) % STG);
        CPCOMMIT();

        const int st = it % STG;
        const uint32_t aSt = sAu + st * ABYTES;
        const uint32_t bSt = sBu + st * BBYTES;
        const uint32_t* Bw = (const uint32_t*)(Bs + st * BK * BN);

        #pragma unroll
        for (int ks = 0; ks < 2; ks++) {
            uint4 af[4];
            #pragma unroll
            for (int im = 0; im < 4; im++)
                af[im] = ldsm4(aSt + aB0 + im * 1024 + ax[ks]);

            uint32_t bf[NI][2];
            if (TRANSB) {
                #pragma unroll
                for (int p = 0; p < NI / 2; p++) {
                    uint4 bv = ldsm4(bSt + bRB[p] + (ks ? bx1 : bx0));
                    bf[2 * p][0] = bv.x; bf[2 * p][1] = bv.y;
                    bf[2 * p + 1][0] = bv.z; bf[2 * p + 1][1] = bv.w;
                }
            } else {
                const int rw = ks ? rw1 : rw0;
                #pragma unroll
                for (int in = 0; in < NI; in++) {
                    bf[in][0] = Bw[rw + colB[in]];
                    bf[in][1] = Bw[rw + colB[in] + 4 * BN];
                }
            }
            #pragma unroll
            for (int im = 0; im < 4; im++)
                #pragma unroll
                for (int in = 0; in < NI; in++)
                    mma8(acc[im][in], (const uint32_t*)&af[im], bf[in]);
        }
    }

    // ---------------- epilogue ----------------
    if constexpr (EPI == 1) {
        float bias_r[4][2];
        #pragma unroll
        for (int im = 0; im < 4; im++)
            #pragma unroll
            for (int h = 0; h < 2; h++)
                bias_r[im][h] = xtra1[(size_t)b * M + m0 + wm + im * 16 + g + 8 * h];

        float qs[NI][2];
        float rs[4][2];
        #pragma unroll
        for (int i = 0; i < NI; i++) { qs[i][0] = 0.f; qs[i][1] = 0.f; }
        #pragma unroll
        for (int i = 0; i < 4; i++)  { rs[i][0] = 0.f; rs[i][1] = 0.f; }

        #pragma unroll
        for (int im = 0; im < 4; im++)
            #pragma unroll
            for (int h = 0; h < 2; h++) {
                int m = m0 + wm + im * 16 + g + 8 * h;
                #pragma unroll
                for (int in = 0; in < NI; in++) {
                    float e0 = __expf(acc[im][in][2 * h]     + bias_r[im][h]);
                    float e1 = __expf(acc[im][in][2 * h + 1] + bias_r[im][h]);
                    float2 v; v.x = e0; v.y = e1;
                    *(float2*)&Cm[(size_t)m * N + n0 + wn + in * 8 + 2 * t] = v;
                    qs[in][0] += e0; qs[in][1] += e1;
                    rs[im][h] += e0 + e1;
                }
            }
        __syncthreads();
        float* red_c = sdyn;            // [2][BN]
        float* red_r = sdyn + 2 * BN;   // [4][BM]
        #pragma unroll
        for (int in = 0; in < NI; in++)
            #pragma unroll
            for (int j = 0; j < 2; j++) {
                float s = qs[in][j];
                s += __shfl_xor_sync(0xffffffffu, s, 16);
                s += __shfl_xor_sync(0xffffffffu, s, 8);
                s += __shfl_xor_sync(0xffffffffu, s, 4);
                if (g == 0) red_c[(w >> 2) * BN + wn + in * 8 + 2 * t + j] = s;
            }
        #pragma unroll
        for (int im = 0; im < 4; im++)
            #pragma unroll
            for (int h = 0; h < 2; h++) {
                float s = rs[im][h];
                s += __shfl_xor_sync(0xffffffffu, s, 1);
                s += __shfl_xor_sync(0xffffffffu, s, 2);
                if (t == 0) red_r[(w & 3) * BM + wm + im * 16 + g + 8 * h] = s;
            }
        __syncthreads();
        if (tid < BN) {
            colpart[((size_t)b * gridDim.y + blockIdx.y) * N + n0 + tid] =
                red_c[tid] + red_c[BN + tid];
        } else if (tid < BN + BM) {
            int m = tid - BN;
            rowpart[((size_t)b * gridDim.x + blockIdx.x) * M + m0 + m] =
                red_r[m] + red_r[BM + m] + red_r[2 * BM + m] + red_r[3 * BM + m];
        }
    } else {
        float sc[NI][2];
        #pragma unroll
        for (int in = 0; in < NI; in++)
            #pragma unroll
            for (int j = 0; j < 2; j++)
                sc[in][j] = xtra1[(size_t)b * N + n0 + wn + in * 8 + 2 * t + j];

        if constexpr (MERGE) {
            // fused assembly: Cm = out + b*4*ND*NCL
            const float* Cin = Cprod + (size_t)b * ND * NCL;
            const int yb = blockIdx.y;
            #pragma unroll
            for (int im = 0; im < 4; im++)
                #pragma unroll
                for (int h = 0; h < 2; h++) {
                    int m = wm + im * 16 + g + 8 * h;
                    #pragma unroll
                    for (int in = 0; in < NI; in++) {
                        int col = n0 + wn + in * 8 + 2 * t;
                        float2 v;
                        v.x = acc[im][in][2 * h]     * sc[in][0];
                        v.y = acc[im][in][2 * h + 1] * sc[in][1];
                        float2 cv = *(const float2*)&Cin[(size_t)m * NCL + col];
                        float2 p; p.x = cv.x * v.x; p.y = cv.y * v.y;
                        if (yb == 0) {
                            *(float2*)&Cm[(size_t)(ND + m) * NCL + col] = v;
                            *(float2*)&Cm[(size_t)(2 * ND + m) * NCL + col] = p;
                        } else {
                            *(float2*)&Cm[(size_t)(3 * ND + m) * NCL + col] = p;
                        }
                    }
                }
        } else {
            #pragma unroll
            for (int im = 0; im < 4; im++)
                #pragma unroll
                for (int h = 0; h < 2; h++) {
                    int m = m0 + wm + im * 16 + g + 8 * h;
                    #pragma unroll
                    for (int in = 0; in < NI; in++) {
                        float2 v;
                        v.x = acc[im][in][2 * h]     * sc[in][0];
                        v.y = acc[im][in][2 * h + 1] * sc[in][1];
                        *(float2*)&Cm[(size_t)m * N + n0 + wn + in * 8 + 2 * t] = v;
                    }
                }
        }
    }
}

// ---------------- combine partial sums -> invl (per q), rinv (per c) --------
__global__ __launch_bounds__(256) void combine_k(
    const float* __restrict__ Lp, const float* __restrict__ Rp,
    float* __restrict__ invl, float* __restrict__ rinv)
{
    int i = blockIdx.x * 256 + threadIdx.x;
    const int nbq = NB * NQL;
    if (i < nbq) {
        int b = i >> 9, q = i & 511;
        float s = 0.f;
        #pragma unroll
        for (int y = 0; y < 8; y++) s += Lp[((size_t)b * 8 + y) * NQL + q];
        invl[i] = 1.f / s;
    } else {
        int j = i - nbq;
        int b = j >> 10, c = j & 1023;
        float s = 0.f;
        #pragma unroll
        for (int x = 0; x < 4; x++) s += Rp[((size_t)b * 4 + x) * NCL + c];
        rinv[j] = 1.f / s;
    }
}

// ---------------- launch ----------------------------------------------------
extern "C" void kernel_launch(void* const* d_in, const int* in_sizes, int n_in,
                              void* d_out, int out_size)
{
    const float* C = (const float*)d_in[0];   // (B, D, CL)
    const float* Q = (const float*)d_in[1];   // (B, D, QL)
    const float* W = (const float*)d_in[2];   // (B*CL, 1, 3D)
    float* out = (float*)d_out;               // (B, 4D, CL)

    float *pAeff, *pbias, *pE2, *pLp, *pRp, *pinvl, *prinv, *pT;
    cudaGetSymbolAddress((void**)&pAeff, g_Aeff);
    cudaGetSymbolAddress((void**)&pbias, g_bias);
    cudaGetSymbolAddress((void**)&pE2,   g_E2);
    cudaGetSymbolAddress((void**)&pLp,   g_Lp);
    cudaGetSymbolAddress((void**)&pRp,   g_Rp);
    cudaGetSymbolAddress((void**)&pinvl, g_invl);
    cudaGetSymbolAddress((void**)&prinv, g_rinv);
    cudaGetSymbolAddress((void**)&pT,    g_T);

    // dynamic smem sizes: STG=4 stages of (A 8KB + B 8KB/4KB)
    const int SM128 = 4 * (8192 + 8192);   // 64 KB
    const int SM64  = 4 * (8192 + 4096);   // 48 KB
    cudaFuncSetAttribute(mma_gemm<false, 1, 128, false>,
                         cudaFuncAttributeMaxDynamicSharedMemorySize, SM128);
    cudaFuncSetAttribute(mma_gemm<false, 2, 64, false>,
                         cudaFuncAttributeMaxDynamicSharedMemorySize, SM64);
    cudaFuncSetAttribute(mma_gemm<true, 2, 128, true>,
                         cudaFuncAttributeMaxDynamicSharedMemorySize, SM128);

    // K0: Aeff + bias + out[sec0] = C
    prep_kernel<<<dim3(NCL / 32, NB), 256>>>(C, W, pAeff, pbias, out);

    // K1: E2 = exp(Aeff @ Q + bias[c]); column+row partial sums
    mma_gemm<false, 1, 128, false><<<dim3(NQL / 128, NCL / 128, NB), 256, SM128>>>(
        pAeff, nullptr, Q, pE2, nullptr, NCL, NQL, ND,
        (size_t)NCL * ND, (size_t)ND * NQL, (size_t)NCL * NQL,
        pbias, pLp, pRp);

    // combine -> invl[b][q], rinv[b][c]
    combine_k<<<NB * (NQL + NCL) / 256, 256>>>(pLp, pRp, pinvl, prinv);

    // K4: T[d][q] = invl[q] * (C @ E2)       (M=D, N=QL, K=CL)
    mma_gemm<false, 2, 64, false><<<dim3(NQL / 64, 1, NB), 256, SM64>>>(
        C, nullptr, pE2, pT, nullptr, ND, NQL, NCL,
        (size_t)ND * NCL, (size_t)NCL * NQL, (size_t)ND * NQL,
        pinvl, nullptr, nullptr);

    // K3+K5 merged + fused assembly:
    //   y=0: v = rinv*(Q @ E2^T) -> out[sec1]=v, out[sec2]=C*v
    //   y=1: v = rinv*(T @ E2^T) -> out[sec3]=C*v
    mma_gemm<true, 2, 128, true><<<dim3(NCL / 128, 2, NB), 256, SM128>>>(
        Q, pT, pE2, out, C, ND, NCL, NQL,
        (size_t)ND * NQL, (size_t)NCL * NQL, (size_t)4 * ND * NCL,
        prinv, nullptr, nullptr);
}

// round 13
// speedup vs baseline: 4.3033x; 1.0085x over previous
#include <cuda_runtime.h>
#include <cstdint>

#define NB  32
#define ND  128
#define NCL 1024
#define NQL 512

// ---------------- scratch (device globals: allocation-free) ----------------
__device__ float g_Aeff[(size_t)NB * NCL * ND];     // Aeff[b][c][d]
__device__ float g_bias[(size_t)NB * NCL];          // bias[b][c]
__device__ float g_E2 [(size_t)NB * NCL * NQL];     // exp(S+bias)  [b][c][q]
__device__ float g_Lp [(size_t)NB * 8 * NQL];       // column partial sums
__device__ float g_Rp [(size_t)NB * 4 * NCL];       // row partial sums
__device__ float g_invl[(size_t)NB * NQL];          // 1 / column sum
__device__ float g_rinv[(size_t)NB * NCL];          // 1 / row sum
__device__ float g_T  [(size_t)NB * ND * NQL];      // T[b][d][q] = S2tC^T

// ---------------- helpers ---------------------------------------------------
__device__ __forceinline__ void mma8(float* d, const uint32_t* a, const uint32_t* b) {
    asm("mma.sync.aligned.m16n8k8.row.col.f32.tf32.tf32.f32 "
        "{%0,%1,%2,%3}, {%4,%5,%6,%7}, {%8,%9}, {%0,%1,%2,%3};"
        : "+f"(d[0]), "+f"(d[1]), "+f"(d[2]), "+f"(d[3])
        : "r"(a[0]), "r"(a[1]), "r"(a[2]), "r"(a[3]), "r"(b[0]), "r"(b[1]));
}
__device__ __forceinline__ uint4 ldsm4(uint32_t addr) {
    uint4 r;
    asm volatile("ldmatrix.sync.aligned.m8n8.x4.shared.b16 {%0,%1,%2,%3}, [%4];"
                 : "=r"(r.x), "=r"(r.y), "=r"(r.z), "=r"(r.w) : "r"(addr));
    return r;
}
#define CP16(dst, src) \
    asm volatile("cp.async.cg.shared.global [%0], [%1], 16;" :: "r"(dst), "l"(src))
#define CPCOMMIT() asm volatile("cp.async.commit_group;" ::)
#define CPWAIT2()  asm volatile("cp.async.wait_group 2;" ::: "memory")

// ---------------- K0: Aeff = wq + wqc*Ct ; bias = wc . Ct ; out[sec0]=C -----
__global__ __launch_bounds__(256) void prep_kernel(
    const float* __restrict__ C, const float* __restrict__ W,
    float* __restrict__ Aeff, float* __restrict__ bias,
    float* __restrict__ out)
{
    __shared__ float Csm[ND][33];
    const int b  = blockIdx.y;
    const int c0 = blockIdx.x * 32;
    const int t  = threadIdx.x;
    const float* Cb = C + (size_t)b * ND * NCL;
    float* Ob = out + (size_t)b * 4 * ND * NCL;

    #pragma unroll
    for (int i = 0; i < 16; i++) {
        int idx = i * 256 + t;
        int d = idx >> 5, c = idx & 31;
        float v = Cb[(size_t)d * NCL + c0 + c];
        Csm[d][c] = v;
        Ob[(size_t)d * NCL + c0 + c] = v;   // out section 0 = C
    }
    __syncthreads();

    #pragma unroll
    for (int i = 0; i < 16; i++) {
        int idx = i * 256 + t;
        int c = idx >> 7, d = idx & 127;
        size_t wb = (size_t)(b * NCL + c0 + c) * 384;
        float wq  = W[wb + d];
        float wqc = W[wb + 256 + d];
        Aeff[(size_t)(b * NCL + c0 + c) * ND + d] = wq + wqc * Csm[d][c];
    }

    int w = t >> 5, lane = t & 31;
    #pragma unroll
    for (int j = 0; j < 4; j++) {
        int c = w + j * 8;
        size_t wb = (size_t)(b * NCL + c0 + c) * 384 + 128;
        float s = 0.f;
        #pragma unroll
        for (int jj = 0; jj < 4; jj++) {
            int d = lane + jj * 32;
            s += W[wb + d] * Csm[d][c];
        }
        #pragma unroll
        for (int off = 16; off; off >>= 1)
            s += __shfl_xor_sync(0xffffffffu, s, off);
        if (lane == 0) bias[b * NCL + c0 + c] = s;
    }
}

// ---------------- tf32 tensor-core GEMM: cp.async + ldmatrix pipeline --------
// 4-stage cp.async ring (3 tiles in flight), dynamic smem, swizzled tiles.
// Warp grid: WM (m) x 8/WM (n).  MI = m-atoms/warp, NI = n-atoms/warp.
// EPI=1: store exp(acc+bias[m]) + col/row partial sums (K1).
// EPI=2 & !MERGE: C = acc * xtra1[col]  (K4 -> T).
// EPI=2 & MERGE : fused final assembly (out sections 1..3).
template <bool TRANSB, int EPI, int BN, bool MERGE, int WM, int OCC>
__global__ __launch_bounds__(256, OCC) void mma_gemm(
    const float* __restrict__ Aall, const float* __restrict__ Aall2,
    const float* __restrict__ Ball,
    float* __restrict__ Call, const float* __restrict__ Cprod,
    int M, int N, int K,
    size_t aStride, size_t bStride, size_t cStride,
    const float* __restrict__ xtra1,
    float* __restrict__ colpart, float* __restrict__ rowpart)
{
    constexpr int BM = 128, BK = 16, STG = 4;
    constexpr int WN = 8 / WM;
    constexpr int MI = BM / (16 * WM);
    constexpr int NI = BN / (8 * WN);
    constexpr int ABYTES = BM * BK * 4;   // 8192
    constexpr int BBYTES = BK * BN * 4;   // 8192 / 4096

    extern __shared__ float sdyn[];
    float* As = sdyn;                          // STG * BM*BK
    float* Bs = sdyn + STG * BM * BK;          // STG * BK*BN

    const int b  = blockIdx.z;
    const int n0 = blockIdx.x * BN;
    const int m0 = MERGE ? 0 : blockIdx.y * BM;
    const float* Abase = MERGE ? (blockIdx.y ? Aall2 : Aall) : Aall;
    const float* A  = Abase + (size_t)b * aStride + (size_t)m0 * K;
    const float* Bp = Ball + (size_t)b * bStride;
    float*       Cm = Call + (size_t)b * cStride;

    const int tid  = threadIdx.x;
    const int w    = tid >> 5;
    const int lane = tid & 31;
    const int g    = lane >> 2;
    const int t    = lane & 3;
    const int wq   = w / WN;                 // m-warp index
    const int wr   = w % WN;                 // n-warp index
    const int wm   = wq * (16 * MI);
    const int wn   = wr * (8 * NI);
    const int na0  = wr * NI;

    const uint32_t sAu = (uint32_t)__cvta_generic_to_shared(As);
    const uint32_t sBu = (uint32_t)__cvta_generic_to_shared(Bs);
    const int T = K / BK;

    // ---- global->smem loader setup (16B chunks, swizzled dst) ----
    const int rA = tid >> 2, cA = tid & 3;
    const float* gA0 = A + (size_t)rA * K + cA * 4;
    const float* gA1 = gA0 + (size_t)64 * K;
    const uint32_t dA0 = sAu + ((rA * 4 + (cA ^ ((rA >> 1) & 3))) << 4);
    const uint32_t dA1 = dA0 + 4096;

    const float* gB0;
    const float* gB1 = nullptr;
    uint32_t dB0, dB1 = 0;
    if (TRANSB) {
        const int rB = tid >> 2, cB = tid & 3;
        gB0 = Bp + (size_t)(n0 + rB) * K + cB * 4;
        dB0 = sBu + ((rB * 4 + (cB ^ ((rB >> 1) & 3))) << 4);
        if (BN == 128) { gB1 = gB0 + (size_t)64 * K; dB1 = dB0 + 4096; }
    } else {
        const int kB = tid >> 4, cB = tid & 15;
        gB0 = Bp + (size_t)kB * N + n0 + cB * 4;
        dB0 = sBu + ((kB * (BN / 4) + (cB ^ (2 * (kB & 3)))) << 4);
        if (BN == 128) { gB1 = gB0 + 64; dB1 = dB0 + 256; }
    }

    auto issue_tile = [&](int stage) {
        const uint32_t ao = stage * ABYTES, bo = stage * BBYTES;
        CP16(dA0 + ao, gA0); CP16(dA1 + ao, gA1);
        gA0 += BK; gA1 += BK;
        CP16(dB0 + bo, gB0);
        if (BN == 128) CP16(dB1 + bo, gB1);
        if (TRANSB) { gB0 += BK; if (BN == 128) gB1 += BK; }
        else        { gB0 += (size_t)BK * N; if (BN == 128) gB1 += (size_t)BK * N; }
    };

    // ---- fragment address precompute ----
    const int aRow = wm + ((lane >> 3) & 1) * 8 + (lane & 7);
    const int aSel = lane >> 4;
    const int fSwz = (lane >> 1) & 3;
    const int aB0  = aRow * 64;
    const int ax[2] = { ((aSel) ^ fSwz) << 4, ((2 + aSel) ^ fSwz) << 4 };

    int bRB[TRANSB ? (NI / 2) : 1];
    int bx0 = 0, bx1 = 0;
    if (TRANSB) {
        const int bSel = (lane >> 3) & 1;
        bx0 = ((bSel) ^ fSwz) << 4;
        bx1 = ((2 + bSel) ^ fSwz) << 4;
        #pragma unroll
        for (int p = 0; p < NI / 2; p++)
            bRB[p] = ((na0 + 2 * p + (lane >> 4)) * 8 + (lane & 7)) * 64;
    }
    int colB[TRANSB ? 1 : NI];
    int rw0 = 0, rw1 = 0;
    if (!TRANSB) {
        #pragma unroll
        for (int in = 0; in < NI; in++) {
            int cn = (wn >> 2) + in * 2 + (g >> 2);
            colB[in] = ((cn ^ (2 * t)) << 2) + (g & 3);
        }
        rw0 = t * BN;
        rw1 = (8 + t) * BN;
    }

    float acc[MI][NI][4];
    #pragma unroll
    for (int i = 0; i < MI; i++)
        #pragma unroll
        for (int j = 0; j < NI; j++)
            #pragma unroll
            for (int r = 0; r < 4; r++) acc[i][j][r] = 0.f;

    // ---- prologue: 3 stages in flight ----
    issue_tile(0); CPCOMMIT();
    issue_tile(1); CPCOMMIT();
    issue_tile(2); CPCOMMIT();

    for (int it = 0; it < T; ++it) {
        CPWAIT2();
        __syncthreads();
        if (it + 3 < T) issue_tile((it + 3) % STG);
        CPCOMMIT();

        const int st = it % STG;
        const uint32_t aSt = sAu + st * ABYTES;
        const uint32_t bSt = sBu + st * BBYTES;
        const uint32_t* Bw = (const uint32_t*)(Bs + st * BK * BN);

        #pragma unroll
        for (int ks = 0; ks < 2; ks++) {
            uint4 af[MI];
            #pragma unroll
            for (int im = 0; im < MI; im++)
                af[im] = ldsm4(aSt + aB0 + im * 1024 + ax[ks]);

            uint32_t bf[NI][2];
            if (TRANSB) {
                #pragma unroll
                for (int p = 0; p < NI / 2; p++) {
                    uint4 bv = ldsm4(bSt + bRB[p] + (ks ? bx1 : bx0));
                    bf[2 * p][0] = bv.x; bf[2 * p][1] = bv.y;
                    bf[2 * p + 1][0] = bv.z; bf[2 * p + 1][1] = bv.w;
                }
            } else {
                const int rw = ks ? rw1 : rw0;
                #pragma unroll
                for (int in = 0; in < NI; in++) {
                    bf[in][0] = Bw[rw + colB[in]];
                    bf[in][1] = Bw[rw + colB[in] + 4 * BN];
                }
            }
            #pragma unroll
            for (int im = 0; im < MI; im++)
                #pragma unroll
                for (int in = 0; in < NI; in++)
                    mma8(acc[im][in], (const uint32_t*)&af[im], bf[in]);
        }
    }

    // ---------------- epilogue ----------------
    if constexpr (EPI == 1) {
        float bias_r[MI][2];
        #pragma unroll
        for (int im = 0; im < MI; im++)
            #pragma unroll
            for (int h = 0; h < 2; h++)
                bias_r[im][h] = xtra1[(size_t)b * M + m0 + wm + im * 16 + g + 8 * h];

        float qs[NI][2];
        float rs[MI][2];
        #pragma unroll
        for (int i = 0; i < NI; i++) { qs[i][0] = 0.f; qs[i][1] = 0.f; }
        #pragma unroll
        for (int i = 0; i < MI; i++) { rs[i][0] = 0.f; rs[i][1] = 0.f; }

        #pragma unroll
        for (int im = 0; im < MI; im++)
            #pragma unroll
            for (int h = 0; h < 2; h++) {
                int m = m0 + wm + im * 16 + g + 8 * h;
                #pragma unroll
                for (int in = 0; in < NI; in++) {
                    float e0 = __expf(acc[im][in][2 * h]     + bias_r[im][h]);
                    float e1 = __expf(acc[im][in][2 * h + 1] + bias_r[im][h]);
                    float2 v; v.x = e0; v.y = e1;
                    *(float2*)&Cm[(size_t)m * N + n0 + wn + in * 8 + 2 * t] = v;
                    qs[in][0] += e0; qs[in][1] += e1;
                    rs[im][h] += e0 + e1;
                }
            }
        __syncthreads();
        float* red_c = sdyn;                 // [WM][BN]
        float* red_r = sdyn + WM * BN;       // [WN][BM]
        #pragma unroll
        for (int in = 0; in < NI; in++)
            #pragma unroll
            for (int j = 0; j < 2; j++) {
                float s = qs[in][j];
                s += __shfl_xor_sync(0xffffffffu, s, 16);
                s += __shfl_xor_sync(0xffffffffu, s, 8);
                s += __shfl_xor_sync(0xffffffffu, s, 4);
                if (g == 0) red_c[wq * BN + wn + in * 8 + 2 * t + j] = s;
            }
        #pragma unroll
        for (int im = 0; im < MI; im++)
            #pragma unroll
            for (int h = 0; h < 2; h++) {
                float s = rs[im][h];
                s += __shfl_xor_sync(0xffffffffu, s, 1);
                s += __shfl_xor_sync(0xffffffffu, s, 2);
                if (t == 0) red_r[wr * BM + wm + im * 16 + g + 8 * h] = s;
            }
        __syncthreads();
        if (tid < BN) {
            float s = 0.f;
            #pragma unroll
            for (int k2 = 0; k2 < WM; k2++) s += red_c[k2 * BN + tid];
            colpart[((size_t)b * gridDim.y + blockIdx.y) * N + n0 + tid] = s;
        } else if (tid < BN + BM) {
            int m = tid - BN;
            float s = 0.f;
            #pragma unroll
            for (int k2 = 0; k2 < WN; k2++) s += red_r[k2 * BM + m];
            rowpart[((size_t)b * gridDim.x + blockIdx.x) * M + m0 + m] = s;
        }
    } else {
        float sc[NI][2];
        #pragma unroll
        for (int in = 0; in < NI; in++)
            #pragma unroll
            for (int j = 0; j < 2; j++)
                sc[in][j] = xtra1[(size_t)b * N + n0 + wn + in * 8 + 2 * t + j];

        if constexpr (MERGE) {
            // fused assembly: Cm = out + b*4*ND*NCL
            const float* Cin = Cprod + (size_t)b * ND * NCL;
            const int yb = blockIdx.y;
            #pragma unroll
            for (int im = 0; im < MI; im++)
                #pragma unroll
                for (int h = 0; h < 2; h++) {
                    int m = wm + im * 16 + g + 8 * h;
                    #pragma unroll
                    for (int in = 0; in < NI; in++) {
                        int col = n0 + wn + in * 8 + 2 * t;
                        float2 v;
                        v.x = acc[im][in][2 * h]     * sc[in][0];
                        v.y = acc[im][in][2 * h + 1] * sc[in][1];
                        float2 cv = *(const float2*)&Cin[(size_t)m * NCL + col];
                        float2 p; p.x = cv.x * v.x; p.y = cv.y * v.y;
                        if (yb == 0) {
                            *(float2*)&Cm[(size_t)(ND + m) * NCL + col] = v;
                            *(float2*)&Cm[(size_t)(2 * ND + m) * NCL + col] = p;
                        } else {
                            *(float2*)&Cm[(size_t)(3 * ND + m) * NCL + col] = p;
                        }
                    }
                }
        } else {
            #pragma unroll
            for (int im = 0; im < MI; im++)
                #pragma unroll
                for (int h = 0; h < 2; h++) {
                    int m = m0 + wm + im * 16 + g + 8 * h;
                    #pragma unroll
                    for (int in = 0; in < NI; in++) {
                        float2 v;
                        v.x = acc[im][in][2 * h]     * sc[in][0];
                        v.y = acc[im][in][2 * h + 1] * sc[in][1];
                        *(float2*)&Cm[(size_t)m * N + n0 + wn + in * 8 + 2 * t] = v;
                    }
                }
        }
    }
}

// ---------------- combine partial sums -> invl (per q), rinv (per c) --------
__global__ __launch_bounds__(256) void combine_k(
    const float* __restrict__ Lp, const float* __restrict__ Rp,
    float* __restrict__ invl, float* __restrict__ rinv)
{
    int i = blockIdx.x * 256 + threadIdx.x;
    const int nbq = NB * NQL;
    if (i < nbq) {
        int b = i >> 9, q = i & 511;
        float s = 0.f;
        #pragma unroll
        for (int y = 0; y < 8; y++) s += Lp[((size_t)b * 8 + y) * NQL + q];
        invl[i] = 1.f / s;
    } else {
        int j = i - nbq;
        int b = j >> 10, c = j & 1023;
        float s = 0.f;
        #pragma unroll
        for (int x = 0; x < 4; x++) s += Rp[((size_t)b * 4 + x) * NCL + c];
        rinv[j] = 1.f / s;
    }
}

// ---------------- launch ----------------------------------------------------
extern "C" void kernel_launch(void* const* d_in, const int* in_sizes, int n_in,
                              void* d_out, int out_size)
{
    const float* C = (const float*)d_in[0];   // (B, D, CL)
    const float* Q = (const float*)d_in[1];   // (B, D, QL)
    const float* W = (const float*)d_in[2];   // (B*CL, 1, 3D)
    float* out = (float*)d_out;               // (B, 4D, CL)

    float *pAeff, *pbias, *pE2, *pLp, *pRp, *pinvl, *prinv, *pT;
    cudaGetSymbolAddress((void**)&pAeff, g_Aeff);
    cudaGetSymbolAddress((void**)&pbias, g_bias);
    cudaGetSymbolAddress((void**)&pE2,   g_E2);
    cudaGetSymbolAddress((void**)&pLp,   g_Lp);
    cudaGetSymbolAddress((void**)&pRp,   g_Rp);
    cudaGetSymbolAddress((void**)&pinvl, g_invl);
    cudaGetSymbolAddress((void**)&prinv, g_rinv);
    cudaGetSymbolAddress((void**)&pT,    g_T);

    // dynamic smem sizes: STG=4 stages of (A 8KB + B 8KB/4KB)
    const int SM128 = 4 * (8192 + 8192);   // 64 KB
    const int SM64  = 4 * (8192 + 4096);   // 48 KB
    cudaFuncSetAttribute(mma_gemm<false, 1, 128, false, 2, 2>,
                         cudaFuncAttributeMaxDynamicSharedMemorySize, SM128);
    cudaFuncSetAttribute(mma_gemm<false, 2, 64, false, 4, 3>,
                         cudaFuncAttributeMaxDynamicSharedMemorySize, SM64);
    cudaFuncSetAttribute(mma_gemm<true, 2, 128, true, 2, 2>,
                         cudaFuncAttributeMaxDynamicSharedMemorySize, SM128);

    // K0: Aeff + bias + out[sec0] = C
    prep_kernel<<<dim3(NCL / 32, NB), 256>>>(C, W, pAeff, pbias, out);

    // K1: E2 = exp(Aeff @ Q + bias[c]); column+row partial sums
    mma_gemm<false, 1, 128, false, 2, 2><<<dim3(NQL / 128, NCL / 128, NB), 256, SM128>>>(
        pAeff, nullptr, Q, pE2, nullptr, NCL, NQL, ND,
        (size_t)NCL * ND, (size_t)ND * NQL, (size_t)NCL * NQL,
        pbias, pLp, pRp);

    // combine -> invl[b][q], rinv[b][c]
    combine_k<<<NB * (NQL + NCL) / 256, 256>>>(pLp, pRp, pinvl, prinv);

    // K4: T[d][q] = invl[q] * (C @ E2)   (M=D, N=QL, K=CL)  4x2 warps, 3 CTAs/SM
    mma_gemm<false, 2, 64, false, 4, 3><<<dim3(NQL / 64, 1, NB), 256, SM64>>>(
        C, nullptr, pE2, pT, nullptr, ND, NQL, NCL,
        (size_t)ND * NCL, (size_t)NCL * NQL, (size_t)ND * NQL,
        pinvl, nullptr, nullptr);

    // K3+K5 merged + fused assembly:
    //   y=0: v = rinv*(Q @ E2^T) -> out[sec1]=v, out[sec2]=C*v
    //   y=1: v = rinv*(T @ E2^T) -> out[sec3]=C*v
    mma_gemm<true, 2, 128, true, 2, 2><<<dim3(NCL / 128, 2, NB), 256, SM128>>>(
        Q, pT, pE2, out, C, ND, NCL, NQL,
        (size_t)ND * NQL, (size_t)NCL * NQL, (size_t)4 * ND * NCL,
        prinv, nullptr, nullptr);
}